// round 14
// baseline (speedup 1.0000x reference)
#include <cuda_runtime.h>
#include <cuda_bf16.h>
#include <math.h>
#include <stdint.h>

// ---------------- shapes ----------------
#define Bb   64
#define Tt   48
#define Hh   512
#define Ee   512
#define ATTN 196
#define AFd  2048
#define FCd  2048
#define Vv   10000
#define CAT4 2048
#define NS   3584

#define OFF_IN   0
#define OFF_OUT  512
#define OFF_CG   1024
#define OFF_F1   1536
#define OFF_F2   2048
#define OFF_QA   2560
#define OFF_QF   3072

// ---------------- tgemm tiling (mma.sync path, baseline PTX) ----------------
#define BM 128
#define BN 128
#define BK 32                         // bf16 K per chunk
#define SPADB 80                      // padded smem row stride in BYTES (40 bf16)
#define TILE_B (128 * SPADB)          // 10240 B per 128x32 bf16 tile
#define STAGE_B (4 * TILE_B)          // Ah Al Bh Bl
#define SMEM_DYN (2 * STAGE_B)        // 81920 B

// ---------------- device scratch ----------------
__device__ float g_fc_emb[Bb * Ee];
__device__ float g_p_att[Bb * ATTN * Hh];
__device__ float g_proj_att[Bb * ATTN * Hh];
__device__ float g_bias_comb[NS];
__device__ float g_S[Bb * NS];
__device__ float g_att_logits[Bb * ATTN];
__device__ float g_att_contrib[Bb * Hh];
__device__ float g_att_contrib0[Bb * Hh];
__device__ float g_h[Bb * Tt * Hh];
__device__ float g_c[Bb * Tt * Hh];

__device__ __align__(128) __nv_bfloat16 g_attfh[Bb * ATTN * AFd];
__device__ __align__(128) __nv_bfloat16 g_attfl[Bb * ATTN * AFd];
__device__ __align__(128) __nv_bfloat16 g_fcfh[Bb * FCd];
__device__ __align__(128) __nv_bfloat16 g_fcfl[Bb * FCd];
__device__ __align__(128) __nv_bfloat16 g_watth[Hh * AFd];
__device__ __align__(128) __nv_bfloat16 g_wattl[Hh * AFd];
__device__ __align__(128) __nv_bfloat16 g_wfch[Ee * FCd];
__device__ __align__(128) __nv_bfloat16 g_wfcl[Ee * FCd];
__device__ __align__(128) __nv_bfloat16 g_wprojh[Hh * AFd];
__device__ __align__(128) __nv_bfloat16 g_wprojl[Hh * AFd];
__device__ __align__(128) __nv_bfloat16 g_wcombh[NS * CAT4];
__device__ __align__(128) __nv_bfloat16 g_wcombl[NS * CAT4];
__device__ __align__(128) __nv_bfloat16 g_wlgh[Vv * Hh];
__device__ __align__(128) __nv_bfloat16 g_wlgl[Vv * Hh];
__device__ __align__(128) __nv_bfloat16 g_cat4h[Bb * CAT4];
__device__ __align__(128) __nv_bfloat16 g_cat4l[Bb * CAT4];
__device__ __align__(128) __nv_bfloat16 g_hh[Bb * Tt * Hh];
__device__ __align__(128) __nv_bfloat16 g_hl[Bb * Tt * Hh];

// ---------------- math helpers ----------------
__device__ __forceinline__ float fsigmoid(float x) { return 1.0f / (1.0f + __expf(-x)); }
__device__ __forceinline__ float ftanh(float x) {
    float e = __expf(2.0f * x);
    return 1.0f - 2.0f / (e + 1.0f);
}

// ---------------- baseline-PTX tensor-core helpers ----------------
__device__ __forceinline__ uint32_t smem_u32(const void* p) {
    uint32_t a;
    asm("{ .reg .u64 t; cvta.to.shared.u64 t, %1; cvt.u32.u64 %0, t; }" : "=r"(a) : "l"(p));
    return a;
}
__device__ __forceinline__ void cp16(uint32_t dst, const void* src, int srcsize) {
    asm volatile("cp.async.cg.shared.global [%0], [%1], 16, %2;"
                 :: "r"(dst), "l"(src), "r"(srcsize));
}
__device__ __forceinline__ void cp_commit() { asm volatile("cp.async.commit_group;"); }
__device__ __forceinline__ void cp_wait1()  { asm volatile("cp.async.wait_group 1;"); }

__device__ __forceinline__ void ldmat4(uint32_t r[4], uint32_t addr) {
    asm volatile("ldmatrix.sync.aligned.m8n8.x4.shared.b16 {%0,%1,%2,%3}, [%4];"
                 : "=r"(r[0]), "=r"(r[1]), "=r"(r[2]), "=r"(r[3]) : "r"(addr));
}
__device__ __forceinline__ void hmma(float c[4], const uint32_t a[4], uint32_t b0, uint32_t b1) {
    asm volatile(
        "mma.sync.aligned.m16n8k16.row.col.f32.bf16.bf16.f32 "
        "{%0,%1,%2,%3}, {%4,%5,%6,%7}, {%8,%9}, {%0,%1,%2,%3};"
        : "+f"(c[0]), "+f"(c[1]), "+f"(c[2]), "+f"(c[3])
        : "r"(a[0]), "r"(a[1]), "r"(a[2]), "r"(a[3]), "r"(b0), "r"(b1));
}

// ---------------- tile loader: 128 rows x 32 bf16 (64B/row), cp.async ----------------
__device__ __forceinline__ void load_tile(const __nv_bfloat16* __restrict__ G, int ld,
                                          int row0, int rowmax, int kt,
                                          uint32_t sm, int tid)
{
#pragma unroll
    for (int t = 0; t < 2; t++) {
        int idx = tid + t * 256;            // 512 chunks of 16B
        int r = idx >> 2, c = idx & 3;
        int gr = row0 + r;
        int ok = (gr < rowmax);
        const void* src = G + (size_t)(ok ? gr : 0) * ld + kt + c * 8;
        cp16(sm + r * SPADB + c * 16, src, ok ? 16 : 0);
    }
}

// ---------------- bf16x3 tensor-core GEMM: C[M,N] = (Ah+Al)(Bh+Bl)^T (+bias) ----------------
// 256 threads = 8 warps: warp grid 2(M) x 4(N); warp tile 64x32.
__global__ void __launch_bounds__(256)
tgemm(const __nv_bfloat16* __restrict__ Ah, const __nv_bfloat16* __restrict__ Al, int lda,
      const __nv_bfloat16* __restrict__ Bh, const __nv_bfloat16* __restrict__ Bl, int ldb,
      const float* __restrict__ bias, float* __restrict__ C, int ldc,
      int M, int N, int K, int ksplit)
{
    extern __shared__ char dsm[];
    const uint32_t smb = smem_u32(dsm);

    const int tid  = threadIdx.x;
    const int wid  = tid >> 5, lane = tid & 31;
    const int wm   = wid & 1;          // 0..1 (M)
    const int wn   = wid >> 1;         // 0..3 (N)
    const int m0   = blockIdx.x * BM;
    const int n0   = blockIdx.y * BN;
    const int klen = K / ksplit;
    const int kbeg = blockIdx.z * klen;
    const int nchunks = klen / BK;

    float acc[4][4][4];
#pragma unroll
    for (int i = 0; i < 4; i++)
#pragma unroll
        for (int j = 0; j < 4; j++)
#pragma unroll
            for (int q = 0; q < 4; q++) acc[i][j][q] = 0.0f;

    // preload chunk 0 -> stage 0
    {
        uint32_t sb = smb;
        load_tile(Ah, lda, m0, M, kbeg, sb,              tid);
        load_tile(Al, lda, m0, M, kbeg, sb + TILE_B,     tid);
        load_tile(Bh, ldb, n0, N, kbeg, sb + 2 * TILE_B, tid);
        load_tile(Bl, ldb, n0, N, kbeg, sb + 3 * TILE_B, tid);
        cp_commit();
    }

    for (int c = 0; c < nchunks; c++) {
        if (c + 1 < nchunks) {
            uint32_t sb = smb + ((c + 1) & 1) * STAGE_B;
            int kt = kbeg + (c + 1) * BK;
            load_tile(Ah, lda, m0, M, kt, sb,              tid);
            load_tile(Al, lda, m0, M, kt, sb + TILE_B,     tid);
            load_tile(Bh, ldb, n0, N, kt, sb + 2 * TILE_B, tid);
            load_tile(Bl, ldb, n0, N, kt, sb + 3 * TILE_B, tid);
        }
        cp_commit();
        cp_wait1();
        __syncthreads();

        const uint32_t sb = smb + (c & 1) * STAGE_B;
#pragma unroll
        for (int ks = 0; ks < 2; ks++) {
            const uint32_t kb = ks * 32 + (lane >> 4) * 16;   // bytes within 64B row
            // A fragments (hi & lo), 4 m-frags of 16x16
            uint32_t ah[4][4], al[4][4];
            const uint32_t arow = wm * 64 + (lane & 15);
#pragma unroll
            for (int i = 0; i < 4; i++) {
                uint32_t ad = (arow + i * 16) * SPADB + kb;
                ldmat4(ah[i], sb + ad);
                ldmat4(al[i], sb + TILE_B + ad);
            }
            // B fragments (hi & lo), 2 x (16 n-rows x 16 k)
            uint32_t bh[2][4], bl[2][4];
            const uint32_t brow = wn * 32 + (lane & 15);
#pragma unroll
            for (int p = 0; p < 2; p++) {
                uint32_t bd = (brow + p * 16) * SPADB + kb;
                ldmat4(bh[p], sb + 2 * TILE_B + bd);
                ldmat4(bl[p], sb + 3 * TILE_B + bd);
            }
#pragma unroll
            for (int i = 0; i < 4; i++)
#pragma unroll
                for (int j = 0; j < 4; j++) {
                    const int p = j >> 1, q = j & 1;   // n-frag j regs = {r[q], r[q+2]}
                    hmma(acc[i][j], ah[i], bh[p][q], bh[p][q + 2]);
                    hmma(acc[i][j], ah[i], bl[p][q], bl[p][q + 2]);
                    hmma(acc[i][j], al[i], bh[p][q], bh[p][q + 2]);
                }
        }
        __syncthreads();
    }

    // epilogue: direct register -> global
    const int rbase = m0 + wm * 64 + (lane >> 2);
    const int cbase = n0 + wn * 32 + (lane & 3) * 2;
#pragma unroll
    for (int i = 0; i < 4; i++) {
#pragma unroll
        for (int j = 0; j < 4; j++) {
            int gc = cbase + j * 8;
            if (gc + 1 >= N + 1) continue;
#pragma unroll
            for (int half = 0; half < 2; half++) {
                int gr = rbase + i * 16 + half * 8;
                if (gr >= M || gc >= N) continue;
                float v0 = acc[i][j][half * 2 + 0];
                float v1 = acc[i][j][half * 2 + 1];
                float* dst = C + (size_t)gr * ldc + gc;
                if (ksplit == 1) {
                    if (bias) { v0 += bias[gc]; v1 += bias[gc + 1]; }
                    if (gc + 1 < N) { float2 v = make_float2(v0, v1); *reinterpret_cast<float2*>(dst) = v; }
                    else dst[0] = v0;
                } else {
                    atomicAdd(dst, v0);
                    if (gc + 1 < N) atomicAdd(dst + 1, v1);
                }
            }
        }
    }
}

// ---------------- fp32 -> bf16 hi/lo split ----------------
__global__ void conv_hilo(const float* __restrict__ src,
                          __nv_bfloat16* __restrict__ hi, __nv_bfloat16* __restrict__ lo, int n)
{
    int i = blockIdx.x * 256 + threadIdx.x;
    if (i < n) {
        float v = src[i];
        __nv_bfloat16 h = __float2bfloat16(v);
        hi[i] = h;
        lo[i] = __float2bfloat16(v - __bfloat162float(h));
    }
}

// W_I attention columns [2048:4096), row stride 4096
__global__ void conv_wproj(const float* __restrict__ wI)
{
    int idx = blockIdx.x * 256 + threadIdx.x;
    if (idx < Hh * AFd) {
        int r = idx >> 11, k = idx & 2047;
        float v = wI[r * 4096 + 2048 + k];
        __nv_bfloat16 h = __float2bfloat16(v);
        g_wprojh[idx] = h;
        g_wprojl[idx] = __float2bfloat16(v - __bfloat162float(h));
    }
}

// ---------------- combined weight build (bf16 hi/lo) ----------------
__global__ void prep_wcomb_kernel(const float* __restrict__ wH, const float* __restrict__ bH,
                                  const float* __restrict__ wI, const float* __restrict__ bI,
                                  const float* __restrict__ wf1, const float* __restrict__ bf1,
                                  const float* __restrict__ wf2, const float* __restrict__ bf2,
                                  const float* __restrict__ wha, const float* __restrict__ bha,
                                  const float* __restrict__ whf, const float* __restrict__ bhf)
{
    int idx = blockIdx.x * 256 + threadIdx.x;
    if (idx < NS * CAT4) {
        int r = idx >> 11;
        int k = idx & 2047;
        float v = 0.0f;
        if (r < 1024) {
            v = wH[r * 2048 + k];
        } else if (r < 1536) {
            v = wI[(r - 1024) * 4096 + k];
        } else if (r < 2048) {
            int rr = r - 1536;
            if (k < 512)                    v = wf1[rr * 1024 + k];
            else if (k >= 1024 && k < 1536) v = wf1[rr * 1024 + 512 + (k - 1024)];
        } else if (r < 2560) {
            int rr = r - 2048;
            if (k >= 512 && k < 1024)       v = wf2[rr * 1024 + (k - 512)];
            else if (k >= 1536)             v = wf2[rr * 1024 + 512 + (k - 1536)];
        } else if (r < 3072) {
            int rr = r - 2560;
            if (k >= 1024 && k < 1536)      v = wha[rr * 512 + (k - 1024)];
        } else {
            int rr = r - 3072;
            if (k >= 1536)                  v = whf[rr * 512 + (k - 1536)];
        }
        __nv_bfloat16 h = __float2bfloat16(v);
        g_wcombh[idx] = h;
        g_wcombl[idx] = __float2bfloat16(v - __bfloat162float(h));
    }
    if (idx < NS) {
        int r = idx;
        float bv;
        if (r < 1024)      bv = bH[r];
        else if (r < 1536) bv = bI[r - 1024];
        else if (r < 2048) bv = bf1[r - 1536];
        else if (r < 2560) bv = bf2[r - 2048];
        else if (r < 3072) bv = bha[r - 2560];
        else               bv = bhf[r - 3072];
        g_bias_comb[r] = bv;
    }
}

__global__ void zero_hc_kernel() {
    int idx = blockIdx.x * 256 + threadIdx.x;
    if (idx < Bb * Tt * Hh) { g_h[idx] = 0.0f; g_c[idx] = 0.0f; }
}

__global__ void contrib0_kernel() {
    int b = blockIdx.x;
    int d = blockIdx.y * 256 + threadIdx.x;
    const float* pj = g_proj_att + ((size_t)b * ATTN) * Hh + d;
    float s = 0.0f;
#pragma unroll 4
    for (int a = 0; a < ATTN; a++) s += pj[(size_t)a * Hh];
    g_att_contrib0[b * Hh + d] = s * (1.0f / (float)ATTN);
}

// gather cat4 (bf16 hi/lo) + init S with combined bias
__global__ void gather_init_kernel(const int* __restrict__ word_idx,
                                   const int* __restrict__ father_idx,
                                   const float* __restrict__ embed_tab,
                                   int i, int first, int use_f)
{
    int b = blockIdx.x;
    int j = blockIdx.y * 256 + threadIdx.x;  // grid (64,14)x256 -> [0,3584)
    g_S[b * NS + j] = g_bias_comb[j];
    if (j < CAT4) {
        float v;
        if (j < 512) {
            if (first) v = g_fc_emb[b * Ee + j];
            else {
                int father = father_idx[b * Tt + i];
                int w = word_idx[b * Tt + father];
                v = embed_tab[(size_t)w * Ee + j];
            }
        } else if (j < 1024) {
            if (use_f) {
                int w = word_idx[b * Tt + (i - 1)];
                v = embed_tab[(size_t)w * Ee + (j - 512)];
            } else v = 0.0f;
        } else if (j < 1536) {
            if (first) v = 0.0f;
            else {
                int father = father_idx[b * Tt + i];
                v = g_h[((size_t)b * Tt + father) * Hh + (j - 1024)];
            }
        } else {
            v = use_f ? g_h[((size_t)b * Tt + (i - 1)) * Hh + (j - 1536)] : 0.0f;
        }
        __nv_bfloat16 h = __float2bfloat16(v);
        g_cat4h[b * CAT4 + j] = h;
        g_cat4l[b * CAT4 + j] = __float2bfloat16(v - __bfloat162float(h));
    }
}

__global__ void att_logits_kernel(const float* __restrict__ W_alpha,
                                  const float* __restrict__ b_alpha)
{
    int b = blockIdx.x;
    int a0 = blockIdx.y * 28;
    int tx = threadIdx.x;
    __shared__ float qs[Hh];
    __shared__ float wal[Hh];
    for (int d = tx; d < Hh; d += 256) {
        qs[d]  = g_S[b * NS + OFF_QA + d] + g_S[b * NS + OFF_QF + d];
        wal[d] = W_alpha[d];
    }
    __syncthreads();
    int warp = tx >> 5, lane = tx & 31;
    for (int a = a0 + warp; a < a0 + 28; a += 8) {
        const float* pa = g_p_att + ((size_t)b * ATTN + a) * Hh;
        float sum = 0.0f;
#pragma unroll 4
        for (int d = lane; d < Hh; d += 32)
            sum += wal[d] * ftanh(qs[d] + pa[d]);
#pragma unroll
        for (int off = 16; off; off >>= 1)
            sum += __shfl_xor_sync(0xFFFFFFFFu, sum, off);
        if (lane == 0) g_att_logits[b * ATTN + a] = sum + b_alpha[0];
    }
}

__global__ void att_contrib_kernel()
{
    int b = blockIdx.x;
    int d0 = blockIdx.y * 128;
    int tx = threadIdx.x;
    __shared__ float w[ATTN];
    __shared__ float red[128];

    float lmx = -3.4e38f;
    for (int a = tx; a < ATTN; a += 128) {
        float v = g_att_logits[b * ATTN + a];
        w[a] = v;
        lmx = fmaxf(lmx, v);
    }
    red[tx] = lmx; __syncthreads();
    for (int s = 64; s; s >>= 1) { if (tx < s) red[tx] = fmaxf(red[tx], red[tx + s]); __syncthreads(); }
    float mx = red[0]; __syncthreads();

    float lsum = 0.0f;
    for (int a = tx; a < ATTN; a += 128) {
        float e = __expf(w[a] - mx);
        w[a] = e;
        lsum += e;
    }
    red[tx] = lsum; __syncthreads();
    for (int s = 64; s; s >>= 1) { if (tx < s) red[tx] += red[tx + s]; __syncthreads(); }
    float inv = 1.0f / red[0];
    __syncthreads();

    const float* pj = g_proj_att + ((size_t)b * ATTN) * Hh + d0 + tx;
    float acc = 0.0f;
#pragma unroll 4
    for (int a = 0; a < ATTN; a++)
        acc += w[a] * pj[(size_t)a * Hh];
    g_att_contrib[b * Hh + d0 + tx] = acc * inv;
}

__global__ void cell_kernel(const int* __restrict__ father_idx,
                            int i, int first, int use_f, int use_mean)
{
    int b = blockIdx.x;
    int h = blockIdx.y * 256 + threadIdx.x;
    const float* Sb = g_S + b * NS;
    const float* attc = (use_mean ? g_att_contrib0 : g_att_contrib) + b * Hh;

    float ing  = fsigmoid(Sb[OFF_IN  + h]);
    float outg = fsigmoid(Sb[OFF_OUT + h]);
    float cg   = ftanh(Sb[OFF_CG + h] + attc[h]);
    float f1   = fsigmoid(Sb[OFF_F1 + h]);
    float f2   = fsigmoid(Sb[OFF_F2 + h]);

    float c1 = 0.0f, c2 = 0.0f;
    if (!first) {
        int father = father_idx[b * Tt + i];
        c1 = g_c[((size_t)b * Tt + father) * Hh + h];
    }
    if (use_f) c2 = g_c[((size_t)b * Tt + (i - 1)) * Hh + h];

    float nc = f1 * c1 + f2 * c2 + ing * cg;
    float nh = outg * ftanh(nc);
    g_h[((size_t)b * Tt + i) * Hh + h] = nh;
    g_c[((size_t)b * Tt + i) * Hh + h] = nc;
}

__global__ void logsoftmax_kernel(float* __restrict__ out)
{
    int row = blockIdx.x;
    float* p = out + (size_t)row * Vv;
    int tx = threadIdx.x;
    __shared__ float red[256];

    float mx = -3.4e38f;
    for (int j = tx; j < Vv; j += 256) mx = fmaxf(mx, p[j]);
    red[tx] = mx; __syncthreads();
    for (int s = 128; s; s >>= 1) { if (tx < s) red[tx] = fmaxf(red[tx], red[tx + s]); __syncthreads(); }
    mx = red[0]; __syncthreads();

    float sum = 0.0f;
    for (int j = tx; j < Vv; j += 256) sum += __expf(p[j] - mx);
    red[tx] = sum; __syncthreads();
    for (int s = 128; s; s >>= 1) { if (tx < s) red[tx] += red[tx + s]; __syncthreads(); }
    float lse = mx + __logf(red[0]);
    __syncthreads();

    for (int j = tx; j < Vv; j += 256) p[j] -= lse;
}

// ---------------- host ----------------
extern "C" void kernel_launch(void* const* d_in, const int* in_sizes, int n_in,
                              void* d_out, int out_size)
{
    const int*   word_idx   = (const int*)  d_in[0];
    const int*   father_idx = (const int*)  d_in[1];
    const float* fc_feats   = (const float*)d_in[2];
    const float* att_feats  = (const float*)d_in[3];
    const float* W_fc       = (const float*)d_in[4];
    const float* b_fc       = (const float*)d_in[5];
    const float* W_att      = (const float*)d_in[6];
    const float* b_att      = (const float*)d_in[7];
    const float* embed_tab  = (const float*)d_in[8];
    const float* wf1        = (const float*)d_in[9];
    const float* bf1        = (const float*)d_in[10];
    const float* wf2        = (const float*)d_in[11];
    const float* bf2        = (const float*)d_in[12];
    const float* wH         = (const float*)d_in[13];
    const float* bH         = (const float*)d_in[14];
    const float* wI         = (const float*)d_in[15];
    const float* bI         = (const float*)d_in[16];
    const float* W_ha       = (const float*)d_in[17];
    const float* b_ha       = (const float*)d_in[18];
    const float* W_hf       = (const float*)d_in[19];
    const float* b_hf       = (const float*)d_in[20];
    const float* W_alpha    = (const float*)d_in[21];
    const float* b_alpha    = (const float*)d_in[22];
    const float* W_logit    = (const float*)d_in[23];
    const float* b_logit    = (const float*)d_in[24];
    float* out = (float*)d_out;

    cudaFuncSetAttribute(tgemm, cudaFuncAttributeMaxDynamicSharedMemorySize, SMEM_DYN);

    void *p_fc, *p_patt, *p_proj, *p_S, *p_h;
    void *p_attfh, *p_attfl, *p_fcfh, *p_fcfl, *p_watth, *p_wattl, *p_wfch, *p_wfcl;
    void *p_wprojh, *p_wprojl, *p_wcombh, *p_wcombl, *p_wlgh, *p_wlgl;
    void *p_cat4h, *p_cat4l, *p_hh, *p_hl;
    cudaGetSymbolAddress(&p_fc,     g_fc_emb);
    cudaGetSymbolAddress(&p_patt,   g_p_att);
    cudaGetSymbolAddress(&p_proj,   g_proj_att);
    cudaGetSymbolAddress(&p_S,      g_S);
    cudaGetSymbolAddress(&p_h,      g_h);
    cudaGetSymbolAddress(&p_attfh,  g_attfh);
    cudaGetSymbolAddress(&p_attfl,  g_attfl);
    cudaGetSymbolAddress(&p_fcfh,   g_fcfh);
    cudaGetSymbolAddress(&p_fcfl,   g_fcfl);
    cudaGetSymbolAddress(&p_watth,  g_watth);
    cudaGetSymbolAddress(&p_wattl,  g_wattl);
    cudaGetSymbolAddress(&p_wfch,   g_wfch);
    cudaGetSymbolAddress(&p_wfcl,   g_wfcl);
    cudaGetSymbolAddress(&p_wprojh, g_wprojh);
    cudaGetSymbolAddress(&p_wprojl, g_wprojl);
    cudaGetSymbolAddress(&p_wcombh, g_wcombh);
    cudaGetSymbolAddress(&p_wcombl, g_wcombl);
    cudaGetSymbolAddress(&p_wlgh,   g_wlgh);
    cudaGetSymbolAddress(&p_wlgl,   g_wlgl);
    cudaGetSymbolAddress(&p_cat4h,  g_cat4h);
    cudaGetSymbolAddress(&p_cat4l,  g_cat4l);
    cudaGetSymbolAddress(&p_hh,     g_hh);
    cudaGetSymbolAddress(&p_hl,     g_hl);

#define BF16P(x) ((__nv_bfloat16*)(x))

    // ---- prep: conversions + combined weight ----
    zero_hc_kernel<<<(Bb * Tt * Hh + 255) / 256, 256>>>();
    conv_hilo<<<(Bb * ATTN * AFd + 255) / 256, 256>>>(att_feats, BF16P(p_attfh), BF16P(p_attfl), Bb * ATTN * AFd);
    conv_hilo<<<(Bb * FCd + 255) / 256, 256>>>(fc_feats, BF16P(p_fcfh), BF16P(p_fcfl), Bb * FCd);
    conv_hilo<<<(Hh * AFd + 255) / 256, 256>>>(W_att, BF16P(p_watth), BF16P(p_wattl), Hh * AFd);
    conv_hilo<<<(Ee * FCd + 255) / 256, 256>>>(W_fc, BF16P(p_wfch), BF16P(p_wfcl), Ee * FCd);
    conv_hilo<<<(Vv * Hh + 255) / 256, 256>>>(W_logit, BF16P(p_wlgh), BF16P(p_wlgl), Vv * Hh);
    conv_wproj<<<(Hh * AFd + 255) / 256, 256>>>(wI);
    prep_wcomb_kernel<<<(NS * CAT4 + 255) / 256, 256>>>(wH, bH, wI, bI, wf1, bf1,
                                                        wf2, bf2, W_ha, b_ha, W_hf, b_hf);

    // fc_emb = fc_feats @ W_fc^T + b_fc     (64 x 512, K=2048)
    tgemm<<<dim3(1, 4, 1), 256, SMEM_DYN>>>(BF16P(p_fcfh), BF16P(p_fcfl), FCd,
                                            BF16P(p_wfch), BF16P(p_wfcl), FCd,
                                            b_fc, (float*)p_fc, Ee, Bb, Ee, FCd, 1);
    // p_att = att_feats @ W_att^T + b_att   (12544 x 512, K=2048)
    tgemm<<<dim3(98, 4, 1), 256, SMEM_DYN>>>(BF16P(p_attfh), BF16P(p_attfl), AFd,
                                             BF16P(p_watth), BF16P(p_wattl), AFd,
                                             b_att, (float*)p_patt, Hh, Bb * ATTN, Hh, AFd, 1);
    // proj_att = att_feats @ W_I_att^T      (12544 x 512, K=2048)
    tgemm<<<dim3(98, 4, 1), 256, SMEM_DYN>>>(BF16P(p_attfh), BF16P(p_attfl), AFd,
                                             BF16P(p_wprojh), BF16P(p_wprojl), AFd,
                                             nullptr, (float*)p_proj, Hh, Bb * ATTN, Hh, AFd, 1);
    contrib0_kernel<<<dim3(Bb, 2), 256>>>();

    // ---- recurrent loop ----
    for (int i = 0; i < Tt; ++i) {
        int first = (i == 0) ? 1 : 0;
        int use_f = (i > 0 && ((i - 1) % 3) != 0) ? 1 : 0;

        gather_init_kernel<<<dim3(Bb, 14), 256>>>(word_idx, father_idx, embed_tab, i, first, use_f);

        // S += cat4 @ Wcomb^T  (64 x 3584, K=2048), split-K=4 with fp32 atomics
        tgemm<<<dim3(1, 28, 4), 256, SMEM_DYN>>>(BF16P(p_cat4h), BF16P(p_cat4l), CAT4,
                                                 BF16P(p_wcombh), BF16P(p_wcombl), CAT4,
                                                 nullptr, (float*)p_S, NS, Bb, NS, CAT4, 4);
        if (!first) {
            att_logits_kernel<<<dim3(Bb, 7), 256>>>(W_alpha, b_alpha);
            att_contrib_kernel<<<dim3(Bb, 4), 128>>>();
        }
        cell_kernel<<<dim3(Bb, 2), 256>>>(father_idx, i, first, use_f, first);
    }

    // ---- logits + log_softmax ----
    conv_hilo<<<(Bb * Tt * Hh + 255) / 256, 256>>>((const float*)p_h, BF16P(p_hh), BF16P(p_hl), Bb * Tt * Hh);
    tgemm<<<dim3(24, 79, 1), 256, SMEM_DYN>>>(BF16P(p_hh), BF16P(p_hl), Hh,
                                              BF16P(p_wlgh), BF16P(p_wlgl), Hh,
                                              b_logit, out, Vv, Bb * Tt, Vv, Hh, 1);
    logsoftmax_kernel<<<Bb * Tt, 256>>>(out);
}

// round 15
// speedup vs baseline: 1.5131x; 1.5131x over previous
#include <cuda_runtime.h>
#include <cuda_bf16.h>
#include <math.h>
#include <stdint.h>

// ---------------- shapes ----------------
#define Bb   64
#define Tt   48
#define Hh   512
#define Ee   512
#define ATTN 196
#define AFd  2048
#define FCd  2048
#define Vv   10000
#define CAT4 2048
#define NS   3584

#define OFF_IN   0
#define OFF_OUT  512
#define OFF_CG   1024
#define OFF_F1   1536
#define OFF_F2   2048
#define OFF_QA   2560
#define OFF_QF   3072

// ---------------- tgemm tiling (mma.sync path, baseline PTX) ----------------
#define BN 128
#define BK 32                         // bf16 K per chunk
#define SPADB 80                      // padded smem row stride in BYTES (40 bf16)

template <int BMT>
struct TG {
    static constexpr int TILE_A  = BMT * SPADB;
    static constexpr int TILE_BB = 128 * SPADB;
    static constexpr int STAGE   = 2 * TILE_A + 2 * TILE_BB;
    static constexpr int SMEM    = 2 * STAGE;
};

// ---------------- device scratch ----------------
__device__ float g_fc_emb[Bb * Ee];
__device__ float g_p_att[Bb * ATTN * Hh];
__device__ float g_proj_att[Bb * ATTN * Hh];
__device__ float g_bias_comb[NS];
__device__ float g_S[Bb * NS];
__device__ float g_att_logits[Bb * ATTN];
__device__ float g_att_contrib0[Bb * Hh];
__device__ float g_h[Bb * Tt * Hh];
__device__ float g_c[Bb * Tt * Hh];

__device__ __align__(128) __nv_bfloat16 g_attfh[Bb * ATTN * AFd];
__device__ __align__(128) __nv_bfloat16 g_attfl[Bb * ATTN * AFd];
__device__ __align__(128) __nv_bfloat16 g_fcfh[Bb * FCd];
__device__ __align__(128) __nv_bfloat16 g_fcfl[Bb * FCd];
__device__ __align__(128) __nv_bfloat16 g_watth[Hh * AFd];
__device__ __align__(128) __nv_bfloat16 g_wattl[Hh * AFd];
__device__ __align__(128) __nv_bfloat16 g_wfch[Ee * FCd];
__device__ __align__(128) __nv_bfloat16 g_wfcl[Ee * FCd];
__device__ __align__(128) __nv_bfloat16 g_wprojh[Hh * AFd];
__device__ __align__(128) __nv_bfloat16 g_wprojl[Hh * AFd];
__device__ __align__(128) __nv_bfloat16 g_wcombh[NS * CAT4];
__device__ __align__(128) __nv_bfloat16 g_wcombl[NS * CAT4];
__device__ __align__(128) __nv_bfloat16 g_wlgh[Vv * Hh];
__device__ __align__(128) __nv_bfloat16 g_wlgl[Vv * Hh];
__device__ __align__(128) __nv_bfloat16 g_cat4h[Bb * CAT4];
__device__ __align__(128) __nv_bfloat16 g_cat4l[Bb * CAT4];
__device__ __align__(128) __nv_bfloat16 g_hh[Bb * Tt * Hh];
__device__ __align__(128) __nv_bfloat16 g_hl[Bb * Tt * Hh];

// ---------------- math helpers ----------------
__device__ __forceinline__ float fsigmoid(float x) { return 1.0f / (1.0f + __expf(-x)); }
__device__ __forceinline__ float ftanh(float x) {
    float e = __expf(2.0f * x);
    return 1.0f - 2.0f / (e + 1.0f);
}
// single-MUFU tanh (MUFU.TANH), used only where error averages out (attention logits)
__device__ __forceinline__ float ftanh_fast(float x) {
    float y;
    asm("tanh.approx.f32 %0, %1;" : "=f"(y) : "f"(x));
    return y;
}

// ---------------- baseline-PTX tensor-core helpers ----------------
__device__ __forceinline__ uint32_t smem_u32(const void* p) {
    uint32_t a;
    asm("{ .reg .u64 t; cvta.to.shared.u64 t, %1; cvt.u32.u64 %0, t; }" : "=r"(a) : "l"(p));
    return a;
}
__device__ __forceinline__ void cp16(uint32_t dst, const void* src, int srcsize) {
    asm volatile("cp.async.cg.shared.global [%0], [%1], 16, %2;"
                 :: "r"(dst), "l"(src), "r"(srcsize));
}
__device__ __forceinline__ void cp_commit() { asm volatile("cp.async.commit_group;"); }
__device__ __forceinline__ void cp_wait1()  { asm volatile("cp.async.wait_group 1;"); }

__device__ __forceinline__ void ldmat4(uint32_t r[4], uint32_t addr) {
    asm volatile("ldmatrix.sync.aligned.m8n8.x4.shared.b16 {%0,%1,%2,%3}, [%4];"
                 : "=r"(r[0]), "=r"(r[1]), "=r"(r[2]), "=r"(r[3]) : "r"(addr));
}
__device__ __forceinline__ void hmma(float c[4], const uint32_t a[4], uint32_t b0, uint32_t b1) {
    asm volatile(
        "mma.sync.aligned.m16n8k16.row.col.f32.bf16.bf16.f32 "
        "{%0,%1,%2,%3}, {%4,%5,%6,%7}, {%8,%9}, {%0,%1,%2,%3};"
        : "+f"(c[0]), "+f"(c[1]), "+f"(c[2]), "+f"(c[3])
        : "r"(a[0]), "r"(a[1]), "r"(a[2]), "r"(a[3]), "r"(b0), "r"(b1));
}

// ---------------- tile loader: ROWS x 32 bf16 (64B/row), cp.async ----------------
template <int ROWS>
__device__ __forceinline__ void load_tile(const __nv_bfloat16* __restrict__ G, int ld,
                                          int row0, int rowmax, int kt,
                                          uint32_t sm, int tid)
{
#pragma unroll
    for (int t = 0; t < ROWS / 64; t++) {
        int idx = tid + t * 256;            // (ROWS*4) chunks of 16B
        int r = idx >> 2, c = idx & 3;
        int gr = row0 + r;
        int ok = (gr < rowmax);
        const void* src = G + (size_t)(ok ? gr : 0) * ld + kt + c * 8;
        cp16(sm + r * SPADB + c * 16, src, ok ? 16 : 0);
    }
}

// ---------------- bf16x3 tensor-core GEMM: C[M,N] = (Ah+Al)(Bh+Bl)^T (+bias) ----------------
// 256 threads = 8 warps: warp grid 2(M) x 4(N); warp tile (BMT/2) x 32.
template <int BMT>
__global__ void __launch_bounds__(256)
tgemm(const __nv_bfloat16* __restrict__ Ah, const __nv_bfloat16* __restrict__ Al, int lda,
      const __nv_bfloat16* __restrict__ Bh, const __nv_bfloat16* __restrict__ Bl, int ldb,
      const float* __restrict__ bias, float* __restrict__ C, int ldc,
      int M, int N, int K, int ksplit)
{
    constexpr int IFR     = BMT / 32;           // 16-row m-frags per warp
    constexpr int TILE_A  = TG<BMT>::TILE_A;
    constexpr int TILE_BB = TG<BMT>::TILE_BB;
    constexpr int STAGE   = TG<BMT>::STAGE;

    extern __shared__ char dsm[];
    const uint32_t smb = smem_u32(dsm);

    const int tid  = threadIdx.x;
    const int wid  = tid >> 5, lane = tid & 31;
    const int wm   = wid & 1;          // 0..1 (M)
    const int wn   = wid >> 1;         // 0..3 (N)
    const int m0   = blockIdx.x * BMT;
    const int n0   = blockIdx.y * BN;
    const int klen = K / ksplit;
    const int kbeg = blockIdx.z * klen;
    const int nchunks = klen / BK;

    float acc[IFR][4][4];
#pragma unroll
    for (int i = 0; i < IFR; i++)
#pragma unroll
        for (int j = 0; j < 4; j++)
#pragma unroll
            for (int q = 0; q < 4; q++) acc[i][j][q] = 0.0f;

    // preload chunk 0 -> stage 0
    {
        uint32_t sb = smb;
        load_tile<BMT>(Ah, lda, m0, M, kbeg, sb,                       tid);
        load_tile<BMT>(Al, lda, m0, M, kbeg, sb + TILE_A,              tid);
        load_tile<128>(Bh, ldb, n0, N, kbeg, sb + 2 * TILE_A,          tid);
        load_tile<128>(Bl, ldb, n0, N, kbeg, sb + 2 * TILE_A + TILE_BB, tid);
        cp_commit();
    }

    for (int c = 0; c < nchunks; c++) {
        if (c + 1 < nchunks) {
            uint32_t sb = smb + ((c + 1) & 1) * STAGE;
            int kt = kbeg + (c + 1) * BK;
            load_tile<BMT>(Ah, lda, m0, M, kt, sb,                       tid);
            load_tile<BMT>(Al, lda, m0, M, kt, sb + TILE_A,              tid);
            load_tile<128>(Bh, ldb, n0, N, kt, sb + 2 * TILE_A,          tid);
            load_tile<128>(Bl, ldb, n0, N, kt, sb + 2 * TILE_A + TILE_BB, tid);
        }
        cp_commit();
        cp_wait1();
        __syncthreads();

        const uint32_t sb = smb + (c & 1) * STAGE;
#pragma unroll
        for (int ks = 0; ks < 2; ks++) {
            const uint32_t kb = ks * 32 + (lane >> 4) * 16;   // bytes within 64B row
            // A fragments (hi & lo)
            uint32_t ah[IFR][4], al[IFR][4];
            const uint32_t arow = wm * (BMT / 2) + (lane & 15);
#pragma unroll
            for (int i = 0; i < IFR; i++) {
                uint32_t ad = (arow + i * 16) * SPADB + kb;
                ldmat4(ah[i], sb + ad);
                ldmat4(al[i], sb + TILE_A + ad);
            }
            // B fragments (hi & lo)
            uint32_t bh[2][4], bl[2][4];
            const uint32_t brow = wn * 32 + (lane & 15);
#pragma unroll
            for (int p = 0; p < 2; p++) {
                uint32_t bd = (brow + p * 16) * SPADB + kb;
                ldmat4(bh[p], sb + 2 * TILE_A + bd);
                ldmat4(bl[p], sb + 2 * TILE_A + TILE_BB + bd);
            }
#pragma unroll
            for (int i = 0; i < IFR; i++)
#pragma unroll
                for (int j = 0; j < 4; j++) {
                    const int p = j >> 1, q = j & 1;
                    hmma(acc[i][j], ah[i], bh[p][q], bh[p][q + 2]);
                    hmma(acc[i][j], ah[i], bl[p][q], bl[p][q + 2]);
                    hmma(acc[i][j], al[i], bh[p][q], bh[p][q + 2]);
                }
        }
        __syncthreads();
    }

    // epilogue: direct register -> global
    const int rbase = m0 + wm * (BMT / 2) + (lane >> 2);
    const int cbase = n0 + wn * 32 + (lane & 3) * 2;
#pragma unroll
    for (int i = 0; i < IFR; i++) {
#pragma unroll
        for (int j = 0; j < 4; j++) {
            int gc = cbase + j * 8;
#pragma unroll
            for (int half = 0; half < 2; half++) {
                int gr = rbase + i * 16 + half * 8;
                if (gr >= M || gc >= N) continue;
                float v0 = acc[i][j][half * 2 + 0];
                float v1 = acc[i][j][half * 2 + 1];
                float* dst = C + (size_t)gr * ldc + gc;
                if (ksplit == 1) {
                    if (bias) { v0 += bias[gc]; v1 += bias[gc + 1]; }
                    if (gc + 1 < N) { float2 v = make_float2(v0, v1); *reinterpret_cast<float2*>(dst) = v; }
                    else dst[0] = v0;
                } else {
                    atomicAdd(dst, v0);
                    if (gc + 1 < N) atomicAdd(dst + 1, v1);
                }
            }
        }
    }
}

// ---------------- fp32 -> bf16 hi/lo split ----------------
__global__ void conv_hilo(const float* __restrict__ src,
                          __nv_bfloat16* __restrict__ hi, __nv_bfloat16* __restrict__ lo, int n)
{
    int i = blockIdx.x * 256 + threadIdx.x;
    if (i < n) {
        float v = src[i];
        __nv_bfloat16 h = __float2bfloat16(v);
        hi[i] = h;
        lo[i] = __float2bfloat16(v - __bfloat162float(h));
    }
}

// W_I attention columns [2048:4096), row stride 4096
__global__ void conv_wproj(const float* __restrict__ wI)
{
    int idx = blockIdx.x * 256 + threadIdx.x;
    if (idx < Hh * AFd) {
        int r = idx >> 11, k = idx & 2047;
        float v = wI[r * 4096 + 2048 + k];
        __nv_bfloat16 h = __float2bfloat16(v);
        g_wprojh[idx] = h;
        g_wprojl[idx] = __float2bfloat16(v - __bfloat162float(h));
    }
}

// ---------------- combined weight build (bf16 hi/lo) ----------------
__global__ void prep_wcomb_kernel(const float* __restrict__ wH, const float* __restrict__ bH,
                                  const float* __restrict__ wI, const float* __restrict__ bI,
                                  const float* __restrict__ wf1, const float* __restrict__ bf1,
                                  const float* __restrict__ wf2, const float* __restrict__ bf2,
                                  const float* __restrict__ wha, const float* __restrict__ bha,
                                  const float* __restrict__ whf, const float* __restrict__ bhf)
{
    int idx = blockIdx.x * 256 + threadIdx.x;
    if (idx < NS * CAT4) {
        int r = idx >> 11;
        int k = idx & 2047;
        float v = 0.0f;
        if (r < 1024) {
            v = wH[r * 2048 + k];
        } else if (r < 1536) {
            v = wI[(r - 1024) * 4096 + k];
        } else if (r < 2048) {
            int rr = r - 1536;
            if (k < 512)                    v = wf1[rr * 1024 + k];
            else if (k >= 1024 && k < 1536) v = wf1[rr * 1024 + 512 + (k - 1024)];
        } else if (r < 2560) {
            int rr = r - 2048;
            if (k >= 512 && k < 1024)       v = wf2[rr * 1024 + (k - 512)];
            else if (k >= 1536)             v = wf2[rr * 1024 + 512 + (k - 1536)];
        } else if (r < 3072) {
            int rr = r - 2560;
            if (k >= 1024 && k < 1536)      v = wha[rr * 512 + (k - 1024)];
        } else {
            int rr = r - 3072;
            if (k >= 1536)                  v = whf[rr * 512 + (k - 1536)];
        }
        __nv_bfloat16 h = __float2bfloat16(v);
        g_wcombh[idx] = h;
        g_wcombl[idx] = __float2bfloat16(v - __bfloat162float(h));
    }
    if (idx < NS) {
        int r = idx;
        float bv;
        if (r < 1024)      bv = bH[r];
        else if (r < 1536) bv = bI[r - 1024];
        else if (r < 2048) bv = bf1[r - 1536];
        else if (r < 2560) bv = bf2[r - 2048];
        else if (r < 3072) bv = bha[r - 2560];
        else               bv = bhf[r - 3072];
        g_bias_comb[r] = bv;
    }
}

__global__ void zero_hc_kernel() {
    int idx = blockIdx.x * 256 + threadIdx.x;
    if (idx < Bb * Tt * Hh) { g_h[idx] = 0.0f; g_c[idx] = 0.0f; }
}

__global__ void contrib0_kernel() {
    int b = blockIdx.x;
    int d = blockIdx.y * 256 + threadIdx.x;
    const float* pj = g_proj_att + ((size_t)b * ATTN) * Hh + d;
    float s = 0.0f;
#pragma unroll 4
    for (int a = 0; a < ATTN; a++) s += pj[(size_t)a * Hh];
    g_att_contrib0[b * Hh + d] = s * (1.0f / (float)ATTN);
}

// gather cat4 (bf16 hi/lo) + init S with combined bias
__global__ void gather_init_kernel(const int* __restrict__ word_idx,
                                   const int* __restrict__ father_idx,
                                   const float* __restrict__ embed_tab,
                                   int i, int first, int use_f)
{
    int b = blockIdx.x;
    int j = blockIdx.y * 256 + threadIdx.x;  // grid (64,14)x256 -> [0,3584)
    g_S[b * NS + j] = g_bias_comb[j];
    if (j < CAT4) {
        float v;
        if (j < 512) {
            if (first) v = g_fc_emb[b * Ee + j];
            else {
                int father = father_idx[b * Tt + i];
                int w = word_idx[b * Tt + father];
                v = embed_tab[(size_t)w * Ee + j];
            }
        } else if (j < 1024) {
            if (use_f) {
                int w = word_idx[b * Tt + (i - 1)];
                v = embed_tab[(size_t)w * Ee + (j - 512)];
            } else v = 0.0f;
        } else if (j < 1536) {
            if (first) v = 0.0f;
            else {
                int father = father_idx[b * Tt + i];
                v = g_h[((size_t)b * Tt + father) * Hh + (j - 1024)];
            }
        } else {
            v = use_f ? g_h[((size_t)b * Tt + (i - 1)) * Hh + (j - 1536)] : 0.0f;
        }
        __nv_bfloat16 h = __float2bfloat16(v);
        g_cat4h[b * CAT4 + j] = h;
        g_cat4l[b * CAT4 + j] = __float2bfloat16(v - __bfloat162float(h));
    }
}

__global__ void att_logits_kernel(const float* __restrict__ W_alpha,
                                  const float* __restrict__ b_alpha)
{
    int b = blockIdx.x;
    int a0 = blockIdx.y * 28;
    int tx = threadIdx.x;
    __shared__ float qs[Hh];
    __shared__ float wal[Hh];
    for (int d = tx; d < Hh; d += 256) {
        qs[d]  = g_S[b * NS + OFF_QA + d] + g_S[b * NS + OFF_QF + d];
        wal[d] = W_alpha[d];
    }
    __syncthreads();
    int warp = tx >> 5, lane = tx & 31;
    for (int a = a0 + warp; a < a0 + 28; a += 8) {
        const float* pa = g_p_att + ((size_t)b * ATTN + a) * Hh;
        float sum = 0.0f;
#pragma unroll 8
        for (int d = lane; d < Hh; d += 32)
            sum += wal[d] * ftanh_fast(qs[d] + pa[d]);
#pragma unroll
        for (int off = 16; off; off >>= 1)
            sum += __shfl_xor_sync(0xFFFFFFFFu, sum, off);
        if (lane == 0) g_att_logits[b * ATTN + a] = sum + b_alpha[0];
    }
}

// fused: softmax over logits + weighted sum of proj_att + LSTM cell pointwise
__global__ void att_contrib_cell_kernel(const int* __restrict__ father_idx,
                                        int i, int use_f)
{
    int b = blockIdx.x;
    int d0 = blockIdx.y * 128;
    int tx = threadIdx.x;
    __shared__ float w[ATTN];
    __shared__ float red[128];

    float lmx = -3.4e38f;
    for (int a = tx; a < ATTN; a += 128) {
        float v = g_att_logits[b * ATTN + a];
        w[a] = v;
        lmx = fmaxf(lmx, v);
    }
    red[tx] = lmx; __syncthreads();
    for (int s = 64; s; s >>= 1) { if (tx < s) red[tx] = fmaxf(red[tx], red[tx + s]); __syncthreads(); }
    float mx = red[0]; __syncthreads();

    float lsum = 0.0f;
    for (int a = tx; a < ATTN; a += 128) {
        float e = __expf(w[a] - mx);
        w[a] = e;
        lsum += e;
    }
    red[tx] = lsum; __syncthreads();
    for (int s = 64; s; s >>= 1) { if (tx < s) red[tx] += red[tx + s]; __syncthreads(); }
    float inv = 1.0f / red[0];
    __syncthreads();

    const int h = d0 + tx;
    const float* pj = g_proj_att + ((size_t)b * ATTN) * Hh + h;
    float acc = 0.0f;
#pragma unroll 4
    for (int a = 0; a < ATTN; a++)
        acc += w[a] * pj[(size_t)a * Hh];
    float attc = acc * inv;

    // ---- cell pointwise (exact tanh/sigmoid; recurrent path) ----
    const float* Sb = g_S + b * NS;
    float ing  = fsigmoid(Sb[OFF_IN  + h]);
    float outg = fsigmoid(Sb[OFF_OUT + h]);
    float cg   = ftanh(Sb[OFF_CG + h] + attc);
    float f1   = fsigmoid(Sb[OFF_F1 + h]);
    float f2   = fsigmoid(Sb[OFF_F2 + h]);

    int father = father_idx[b * Tt + i];
    float c1 = g_c[((size_t)b * Tt + father) * Hh + h];
    float c2 = use_f ? g_c[((size_t)b * Tt + (i - 1)) * Hh + h] : 0.0f;

    float nc = f1 * c1 + f2 * c2 + ing * cg;
    float nh = outg * ftanh(nc);
    g_h[((size_t)b * Tt + i) * Hh + h] = nh;
    g_c[((size_t)b * Tt + i) * Hh + h] = nc;
}

// step-0 cell (uses mean attention contribution; no parents)
__global__ void cell0_kernel()
{
    int b = blockIdx.x;
    int h = blockIdx.y * 256 + threadIdx.x;
    const float* Sb = g_S + b * NS;
    float attc = g_att_contrib0[b * Hh + h];

    float ing  = fsigmoid(Sb[OFF_IN  + h]);
    float outg = fsigmoid(Sb[OFF_OUT + h]);
    float cg   = ftanh(Sb[OFF_CG + h] + attc);

    float nc = ing * cg;
    float nh = outg * ftanh(nc);
    g_h[(size_t)b * Tt * Hh + h] = nh;
    g_c[(size_t)b * Tt * Hh + h] = nc;
}

__global__ void logsoftmax_kernel(float* __restrict__ out)
{
    int row = blockIdx.x;
    float* p = out + (size_t)row * Vv;
    int tx = threadIdx.x;
    __shared__ float red[256];

    float mx = -3.4e38f;
    for (int j = tx; j < Vv; j += 256) mx = fmaxf(mx, p[j]);
    red[tx] = mx; __syncthreads();
    for (int s = 128; s; s >>= 1) { if (tx < s) red[tx] = fmaxf(red[tx], red[tx + s]); __syncthreads(); }
    mx = red[0]; __syncthreads();

    float sum = 0.0f;
    for (int j = tx; j < Vv; j += 256) sum += __expf(p[j] - mx);
    red[tx] = sum; __syncthreads();
    for (int s = 128; s; s >>= 1) { if (tx < s) red[tx] += red[tx + s]; __syncthreads(); }
    float lse = mx + __logf(red[0]);
    __syncthreads();

    for (int j = tx; j < Vv; j += 256) p[j] -= lse;
}

// ---------------- host ----------------
extern "C" void kernel_launch(void* const* d_in, const int* in_sizes, int n_in,
                              void* d_out, int out_size)
{
    const int*   word_idx   = (const int*)  d_in[0];
    const int*   father_idx = (const int*)  d_in[1];
    const float* fc_feats   = (const float*)d_in[2];
    const float* att_feats  = (const float*)d_in[3];
    const float* W_fc       = (const float*)d_in[4];
    const float* b_fc       = (const float*)d_in[5];
    const float* W_att      = (const float*)d_in[6];
    const float* b_att      = (const float*)d_in[7];
    const float* embed_tab  = (const float*)d_in[8];
    const float* wf1        = (const float*)d_in[9];
    const float* bf1        = (const float*)d_in[10];
    const float* wf2        = (const float*)d_in[11];
    const float* bf2        = (const float*)d_in[12];
    const float* wH         = (const float*)d_in[13];
    const float* bH         = (const float*)d_in[14];
    const float* wI         = (const float*)d_in[15];
    const float* bI         = (const float*)d_in[16];
    const float* W_ha       = (const float*)d_in[17];
    const float* b_ha       = (const float*)d_in[18];
    const float* W_hf       = (const float*)d_in[19];
    const float* b_hf       = (const float*)d_in[20];
    const float* W_alpha    = (const float*)d_in[21];
    const float* b_alpha    = (const float*)d_in[22];
    const float* W_logit    = (const float*)d_in[23];
    const float* b_logit    = (const float*)d_in[24];
    float* out = (float*)d_out;

    cudaFuncSetAttribute(tgemm<128>, cudaFuncAttributeMaxDynamicSharedMemorySize, TG<128>::SMEM);
    cudaFuncSetAttribute(tgemm<64>,  cudaFuncAttributeMaxDynamicSharedMemorySize, TG<64>::SMEM);

    void *p_fc, *p_patt, *p_proj, *p_S, *p_h;
    void *p_attfh, *p_attfl, *p_fcfh, *p_fcfl, *p_watth, *p_wattl, *p_wfch, *p_wfcl;
    void *p_wprojh, *p_wprojl, *p_wcombh, *p_wcombl, *p_wlgh, *p_wlgl;
    void *p_cat4h, *p_cat4l, *p_hh, *p_hl;
    cudaGetSymbolAddress(&p_fc,     g_fc_emb);
    cudaGetSymbolAddress(&p_patt,   g_p_att);
    cudaGetSymbolAddress(&p_proj,   g_proj_att);
    cudaGetSymbolAddress(&p_S,      g_S);
    cudaGetSymbolAddress(&p_h,      g_h);
    cudaGetSymbolAddress(&p_attfh,  g_attfh);
    cudaGetSymbolAddress(&p_attfl,  g_attfl);
    cudaGetSymbolAddress(&p_fcfh,   g_fcfh);
    cudaGetSymbolAddress(&p_fcfl,   g_fcfl);
    cudaGetSymbolAddress(&p_watth,  g_watth);
    cudaGetSymbolAddress(&p_wattl,  g_wattl);
    cudaGetSymbolAddress(&p_wfch,   g_wfch);
    cudaGetSymbolAddress(&p_wfcl,   g_wfcl);
    cudaGetSymbolAddress(&p_wprojh, g_wprojh);
    cudaGetSymbolAddress(&p_wprojl, g_wprojl);
    cudaGetSymbolAddress(&p_wcombh, g_wcombh);
    cudaGetSymbolAddress(&p_wcombl, g_wcombl);
    cudaGetSymbolAddress(&p_wlgh,   g_wlgh);
    cudaGetSymbolAddress(&p_wlgl,   g_wlgl);
    cudaGetSymbolAddress(&p_cat4h,  g_cat4h);
    cudaGetSymbolAddress(&p_cat4l,  g_cat4l);
    cudaGetSymbolAddress(&p_hh,     g_hh);
    cudaGetSymbolAddress(&p_hl,     g_hl);

#define BF16P(x) ((__nv_bfloat16*)(x))

    // ---- prep: conversions + combined weight ----
    zero_hc_kernel<<<(Bb * Tt * Hh + 255) / 256, 256>>>();
    conv_hilo<<<(Bb * ATTN * AFd + 255) / 256, 256>>>(att_feats, BF16P(p_attfh), BF16P(p_attfl), Bb * ATTN * AFd);
    conv_hilo<<<(Bb * FCd + 255) / 256, 256>>>(fc_feats, BF16P(p_fcfh), BF16P(p_fcfl), Bb * FCd);
    conv_hilo<<<(Hh * AFd + 255) / 256, 256>>>(W_att, BF16P(p_watth), BF16P(p_wattl), Hh * AFd);
    conv_hilo<<<(Ee * FCd + 255) / 256, 256>>>(W_fc, BF16P(p_wfch), BF16P(p_wfcl), Ee * FCd);
    conv_hilo<<<(Vv * Hh + 255) / 256, 256>>>(W_logit, BF16P(p_wlgh), BF16P(p_wlgl), Vv * Hh);
    conv_wproj<<<(Hh * AFd + 255) / 256, 256>>>(wI);
    prep_wcomb_kernel<<<(NS * CAT4 + 255) / 256, 256>>>(wH, bH, wI, bI, wf1, bf1,
                                                        wf2, bf2, W_ha, b_ha, W_hf, b_hf);

    // fc_emb = fc_feats @ W_fc^T + b_fc     (64 x 512, K=2048)
    tgemm<64><<<dim3(1, 4, 1), 256, TG<64>::SMEM>>>(BF16P(p_fcfh), BF16P(p_fcfl), FCd,
                                                    BF16P(p_wfch), BF16P(p_wfcl), FCd,
                                                    b_fc, (float*)p_fc, Ee, Bb, Ee, FCd, 1);
    // p_att = att_feats @ W_att^T + b_att   (12544 x 512, K=2048)
    tgemm<128><<<dim3(98, 4, 1), 256, TG<128>::SMEM>>>(BF16P(p_attfh), BF16P(p_attfl), AFd,
                                                       BF16P(p_watth), BF16P(p_wattl), AFd,
                                                       b_att, (float*)p_patt, Hh, Bb * ATTN, Hh, AFd, 1);
    // proj_att = att_feats @ W_I_att^T      (12544 x 512, K=2048)
    tgemm<128><<<dim3(98, 4, 1), 256, TG<128>::SMEM>>>(BF16P(p_attfh), BF16P(p_attfl), AFd,
                                                       BF16P(p_wprojh), BF16P(p_wprojl), AFd,
                                                       nullptr, (float*)p_proj, Hh, Bb * ATTN, Hh, AFd, 1);
    contrib0_kernel<<<dim3(Bb, 2), 256>>>();

    // ---- recurrent loop ----
    for (int i = 0; i < Tt; ++i) {
        int first = (i == 0) ? 1 : 0;
        int use_f = (i > 0 && ((i - 1) % 3) != 0) ? 1 : 0;

        gather_init_kernel<<<dim3(Bb, 14), 256>>>(word_idx, father_idx, embed_tab, i, first, use_f);

        // S += cat4 @ Wcomb^T  (64 x 3584, K=2048), split-K=4 with fp32 atomics
        tgemm<64><<<dim3(1, 28, 4), 256, TG<64>::SMEM>>>(BF16P(p_cat4h), BF16P(p_cat4l), CAT4,
                                                         BF16P(p_wcombh), BF16P(p_wcombl), CAT4,
                                                         nullptr, (float*)p_S, NS, Bb, NS, CAT4, 4);
        if (first) {
            cell0_kernel<<<dim3(Bb, 2), 256>>>();
        } else {
            att_logits_kernel<<<dim3(Bb, 7), 256>>>(W_alpha, b_alpha);
            att_contrib_cell_kernel<<<dim3(Bb, 4), 128>>>(father_idx, i, use_f);
        }
    }

    // ---- logits + log_softmax ----
    conv_hilo<<<(Bb * Tt * Hh + 255) / 256, 256>>>((const float*)p_h, BF16P(p_hh), BF16P(p_hl), Bb * Tt * Hh);
    tgemm<128><<<dim3(24, 79, 1), 256, TG<128>::SMEM>>>(BF16P(p_hh), BF16P(p_hl), Hh,
                                                        BF16P(p_wlgh), BF16P(p_wlgl), Hh,
                                                        b_logit, out, Vv, Bb * Tt, Vv, Hh, 1);
    logsoftmax_kernel<<<Bb * Tt, 256>>>(out);
}

// round 16
// speedup vs baseline: 1.5765x; 1.0419x over previous
#include <cuda_runtime.h>
#include <cuda_bf16.h>
#include <math.h>
#include <stdint.h>

// ---------------- shapes ----------------
#define Bb   64
#define Tt   48
#define Hh   512
#define Ee   512
#define ATTN 196
#define AFd  2048
#define FCd  2048
#define Vv   10000
#define CAT4 2048
#define NS   3584

#define OFF_IN   0
#define OFF_OUT  512
#define OFF_CG   1024
#define OFF_F1   1536
#define OFF_F2   2048
#define OFF_QA   2560
#define OFF_QF   3072

// ---------------- tgemm tiling (mma.sync path, baseline PTX) ----------------
#define BN 128
#define BK 32                         // bf16 K per chunk
#define SPADB 80                      // padded smem row stride in BYTES (40 bf16)

template <int BMT>
struct TG {
    static constexpr int TILE_A  = BMT * SPADB;
    static constexpr int TILE_BB = 128 * SPADB;
    static constexpr int STAGE   = 2 * TILE_A + 2 * TILE_BB;
    static constexpr int SMEM    = 2 * STAGE;
};

// step_gemm smem layout
#define SG_TILE_A  (64 * SPADB)                   // 5120
#define SG_CHUNKS  16
#define SG_ABYTES  (SG_CHUNKS * 2 * SG_TILE_A)    // 163840
#define SG_TILE_B  (128 * SPADB)                  // 10240
#define SG_BSTAGE  (2 * SG_TILE_B)                // 20480
#define SG_SMEM    (SG_ABYTES + 2 * SG_BSTAGE)    // 204800

// ---------------- device scratch ----------------
__device__ float g_fc_emb[Bb * Ee];
__device__ float g_p_att[Bb * ATTN * Hh];
__device__ float g_proj_att[Bb * ATTN * Hh];
__device__ float g_bias_comb[NS];
__device__ float g_Sp[4][Bb * NS];
__device__ float g_att_contrib0[Bb * Hh];
__device__ float g_h[Bb * Tt * Hh];
__device__ float g_c[Bb * Tt * Hh];

__device__ __align__(128) __nv_bfloat16 g_attfh[Bb * ATTN * AFd];
__device__ __align__(128) __nv_bfloat16 g_attfl[Bb * ATTN * AFd];
__device__ __align__(128) __nv_bfloat16 g_fcfh[Bb * FCd];
__device__ __align__(128) __nv_bfloat16 g_fcfl[Bb * FCd];
__device__ __align__(128) __nv_bfloat16 g_watth[Hh * AFd];
__device__ __align__(128) __nv_bfloat16 g_wattl[Hh * AFd];
__device__ __align__(128) __nv_bfloat16 g_wfch[Ee * FCd];
__device__ __align__(128) __nv_bfloat16 g_wfcl[Ee * FCd];
__device__ __align__(128) __nv_bfloat16 g_wprojh[Hh * AFd];
__device__ __align__(128) __nv_bfloat16 g_wprojl[Hh * AFd];
__device__ __align__(128) __nv_bfloat16 g_wcombh[NS * CAT4];
__device__ __align__(128) __nv_bfloat16 g_wcombl[NS * CAT4];
__device__ __align__(128) __nv_bfloat16 g_wlgh[Vv * Hh];
__device__ __align__(128) __nv_bfloat16 g_wlgl[Vv * Hh];
__device__ __align__(128) __nv_bfloat16 g_hh[Bb * Tt * Hh];
__device__ __align__(128) __nv_bfloat16 g_hl[Bb * Tt * Hh];

// ---------------- math helpers ----------------
__device__ __forceinline__ float fsigmoid(float x) { return 1.0f / (1.0f + __expf(-x)); }
__device__ __forceinline__ float ftanh(float x) {
    float e = __expf(2.0f * x);
    return 1.0f - 2.0f / (e + 1.0f);
}
__device__ __forceinline__ float ftanh_fast(float x) {
    float y;
    asm("tanh.approx.f32 %0, %1;" : "=f"(y) : "f"(x));
    return y;
}

// ---------------- baseline-PTX tensor-core helpers ----------------
__device__ __forceinline__ uint32_t smem_u32(const void* p) {
    uint32_t a;
    asm("{ .reg .u64 t; cvta.to.shared.u64 t, %1; cvt.u32.u64 %0, t; }" : "=r"(a) : "l"(p));
    return a;
}
__device__ __forceinline__ void cp16(uint32_t dst, const void* src, int srcsize) {
    asm volatile("cp.async.cg.shared.global [%0], [%1], 16, %2;"
                 :: "r"(dst), "l"(src), "r"(srcsize));
}
__device__ __forceinline__ void cp_commit() { asm volatile("cp.async.commit_group;"); }
__device__ __forceinline__ void cp_wait1()  { asm volatile("cp.async.wait_group 1;"); }
__device__ __forceinline__ void cp_wait0()  { asm volatile("cp.async.wait_group 0;"); }

__device__ __forceinline__ void ldmat4(uint32_t r[4], uint32_t addr) {
    asm volatile("ldmatrix.sync.aligned.m8n8.x4.shared.b16 {%0,%1,%2,%3}, [%4];"
                 : "=r"(r[0]), "=r"(r[1]), "=r"(r[2]), "=r"(r[3]) : "r"(addr));
}
__device__ __forceinline__ void hmma(float c[4], const uint32_t a[4], uint32_t b0, uint32_t b1) {
    asm volatile(
        "mma.sync.aligned.m16n8k16.row.col.f32.bf16.bf16.f32 "
        "{%0,%1,%2,%3}, {%4,%5,%6,%7}, {%8,%9}, {%0,%1,%2,%3};"
        : "+f"(c[0]), "+f"(c[1]), "+f"(c[2]), "+f"(c[3])
        : "r"(a[0]), "r"(a[1]), "r"(a[2]), "r"(a[3]), "r"(b0), "r"(b1));
}

// pack 4 floats -> two bf16x2 words (hi) + two bf16x2 words (lo residual)
__device__ __forceinline__ void pack_hilo4(float4 v, uint32_t h[2], uint32_t l[2]) {
    __nv_bfloat162 h0 = __floats2bfloat162_rn(v.x, v.y);
    __nv_bfloat162 h1 = __floats2bfloat162_rn(v.z, v.w);
    __nv_bfloat162 l0 = __floats2bfloat162_rn(v.x - __low2float(h0), v.y - __high2float(h0));
    __nv_bfloat162 l1 = __floats2bfloat162_rn(v.z - __low2float(h1), v.w - __high2float(h1));
    h[0] = *(uint32_t*)&h0; h[1] = *(uint32_t*)&h1;
    l[0] = *(uint32_t*)&l0; l[1] = *(uint32_t*)&l1;
}

// ---------------- tile loader: ROWS x 32 bf16 (64B/row), cp.async ----------------
template <int ROWS>
__device__ __forceinline__ void load_tile(const __nv_bfloat16* __restrict__ G, int ld,
                                          int row0, int rowmax, int kt,
                                          uint32_t sm, int tid)
{
#pragma unroll
    for (int t = 0; t < ROWS / 64; t++) {
        int idx = tid + t * 256;
        int r = idx >> 2, c = idx & 3;
        int gr = row0 + r;
        int ok = (gr < rowmax);
        const void* src = G + (size_t)(ok ? gr : 0) * ld + kt + c * 8;
        cp16(sm + r * SPADB + c * 16, src, ok ? 16 : 0);
    }
}

// ---------------- generic bf16x3 tensor-core GEMM (prep + logits) ----------------
template <int BMT>
__global__ void __launch_bounds__(256)
tgemm(const __nv_bfloat16* __restrict__ Ah, const __nv_bfloat16* __restrict__ Al, int lda,
      const __nv_bfloat16* __restrict__ Bh, const __nv_bfloat16* __restrict__ Bl, int ldb,
      const float* __restrict__ bias, float* __restrict__ C, int ldc,
      int M, int N, int K)
{
    constexpr int IFR     = BMT / 32;
    constexpr int TILE_A  = TG<BMT>::TILE_A;
    constexpr int TILE_BB = TG<BMT>::TILE_BB;
    constexpr int STAGE   = TG<BMT>::STAGE;

    extern __shared__ char dsm[];
    const uint32_t smb = smem_u32(dsm);

    const int tid  = threadIdx.x;
    const int wid  = tid >> 5, lane = tid & 31;
    const int wm   = wid & 1;
    const int wn   = wid >> 1;
    const int m0   = blockIdx.x * BMT;
    const int n0   = blockIdx.y * BN;
    const int nchunks = K / BK;

    float acc[IFR][4][4];
#pragma unroll
    for (int i = 0; i < IFR; i++)
#pragma unroll
        for (int j = 0; j < 4; j++)
#pragma unroll
            for (int q = 0; q < 4; q++) acc[i][j][q] = 0.0f;

    {
        uint32_t sb = smb;
        load_tile<BMT>(Ah, lda, m0, M, 0, sb,                        tid);
        load_tile<BMT>(Al, lda, m0, M, 0, sb + TILE_A,               tid);
        load_tile<128>(Bh, ldb, n0, N, 0, sb + 2 * TILE_A,           tid);
        load_tile<128>(Bl, ldb, n0, N, 0, sb + 2 * TILE_A + TILE_BB, tid);
        cp_commit();
    }

    for (int c = 0; c < nchunks; c++) {
        if (c + 1 < nchunks) {
            uint32_t sb = smb + ((c + 1) & 1) * STAGE;
            int kt = (c + 1) * BK;
            load_tile<BMT>(Ah, lda, m0, M, kt, sb,                        tid);
            load_tile<BMT>(Al, lda, m0, M, kt, sb + TILE_A,               tid);
            load_tile<128>(Bh, ldb, n0, N, kt, sb + 2 * TILE_A,           tid);
            load_tile<128>(Bl, ldb, n0, N, kt, sb + 2 * TILE_A + TILE_BB, tid);
            cp_commit();
            cp_wait1();
        } else {
            cp_wait0();
        }
        __syncthreads();

        const uint32_t sb = smb + (c & 1) * STAGE;
#pragma unroll
        for (int ks = 0; ks < 2; ks++) {
            const uint32_t kb = ks * 32 + (lane >> 4) * 16;
            uint32_t ah[IFR][4], al[IFR][4];
            const uint32_t arow = wm * (BMT / 2) + (lane & 15);
#pragma unroll
            for (int i = 0; i < IFR; i++) {
                uint32_t ad = (arow + i * 16) * SPADB + kb;
                ldmat4(ah[i], sb + ad);
                ldmat4(al[i], sb + TILE_A + ad);
            }
            uint32_t bh[2][4], bl[2][4];
            const uint32_t brow = wn * 32 + (lane & 15);
#pragma unroll
            for (int p = 0; p < 2; p++) {
                uint32_t bd = (brow + p * 16) * SPADB + kb;
                ldmat4(bh[p], sb + 2 * TILE_A + bd);
                ldmat4(bl[p], sb + 2 * TILE_A + TILE_BB + bd);
            }
#pragma unroll
            for (int i = 0; i < IFR; i++)
#pragma unroll
                for (int j = 0; j < 4; j++) {
                    const int p = j >> 1, q = j & 1;
                    hmma(acc[i][j], ah[i], bh[p][q], bh[p][q + 2]);
                    hmma(acc[i][j], ah[i], bl[p][q], bl[p][q + 2]);
                    hmma(acc[i][j], al[i], bh[p][q], bh[p][q + 2]);
                }
        }
        __syncthreads();
    }

    const int rbase = m0 + wm * (BMT / 2) + (lane >> 2);
    const int cbase = n0 + wn * 32 + (lane & 3) * 2;
#pragma unroll
    for (int i = 0; i < IFR; i++) {
#pragma unroll
        for (int j = 0; j < 4; j++) {
            int gc = cbase + j * 8;
#pragma unroll
            for (int half = 0; half < 2; half++) {
                int gr = rbase + i * 16 + half * 8;
                if (gr >= M || gc >= N) continue;
                float v0 = acc[i][j][half * 2 + 0];
                float v1 = acc[i][j][half * 2 + 1];
                if (bias) { v0 += bias[gc]; if (gc + 1 < N) v1 += bias[gc + 1]; }
                float* dst = C + (size_t)gr * ldc + gc;
                if (gc + 1 < N) { float2 v = make_float2(v0, v1); *reinterpret_cast<float2*>(dst) = v; }
                else dst[0] = v0;
            }
        }
    }
}

// ---------------- fused per-step GEMM: gather + bf16x3 MMA -> partial S ----------------
// grid (1, 28, 4): y = 128-col tile of NS, z = cat4 segment {x1, x2, h1, h2}
__global__ void __launch_bounds__(256)
step_gemm(const int* __restrict__ word_idx, const int* __restrict__ father_idx,
          const float* __restrict__ embed_tab, int i, int first, int use_f)
{
    extern __shared__ char dsm[];
    __shared__ const float* srcrow[64];

    const int tid = threadIdx.x;
    const int wid = tid >> 5, lane = tid & 31;
    const int wm  = wid & 1;
    const int wn  = wid >> 1;
    const int z   = blockIdx.z;
    const int n0  = blockIdx.y * 128;
    const int kseg = z * 512;

    const uint32_t smb = smem_u32(dsm);
    const uint32_t smB = smb + SG_ABYTES;

    // per-row source pointers for this segment
    if (tid < 64) {
        int b = tid;
        const float* p = nullptr;
        if (z == 0) {
            if (first) p = g_fc_emb + b * Ee;
            else {
                int father = father_idx[b * Tt + i];
                int w = word_idx[b * Tt + father];
                p = embed_tab + (size_t)w * Ee;
            }
        } else if (z == 1) {
            if (use_f) {
                int w = word_idx[b * Tt + (i - 1)];
                p = embed_tab + (size_t)w * Ee;
            }
        } else if (z == 2) {
            if (!first) {
                int father = father_idx[b * Tt + i];
                p = g_h + ((size_t)b * Tt + father) * Hh;
            }
        } else {
            if (use_f) p = g_h + ((size_t)b * Tt + (i - 1)) * Hh;
        }
        srcrow[b] = p;
    }

    // kick off B chunk 0 while we gather A
    load_tile<128>(g_wcombh, CAT4, n0, NS, kseg, smB,              tid);
    load_tile<128>(g_wcombl, CAT4, n0, NS, kseg, smB + SG_TILE_B,  tid);
    cp_commit();
    __syncthreads();   // srcrow visible

    // gather A segment: 64 x 512 fp32 -> hi/lo bf16, chunk-tiled smem
#pragma unroll 4
    for (int t = 0; t < 32; t++) {
        int idx = t * 256 + tid;            // 8192 float4 slots
        int r = idx >> 7;                    // 128 float4 per row
        int c4 = (idx & 127) * 4;
        const float* p = srcrow[r];
        float4 v = p ? *(const float4*)(p + c4) : make_float4(0.f, 0.f, 0.f, 0.f);
        uint32_t h[2], l[2];
        pack_hilo4(v, h, l);
        int ch = c4 >> 5, cc = c4 & 31;
        char* base = dsm + ch * (2 * SG_TILE_A) + r * SPADB + cc * 2;
        *(uint32_t*)(base)                  = h[0];
        *(uint32_t*)(base + 4)              = h[1];
        *(uint32_t*)(base + SG_TILE_A)      = l[0];
        *(uint32_t*)(base + SG_TILE_A + 4)  = l[1];
    }

    float acc[2][4][4];
#pragma unroll
    for (int i2 = 0; i2 < 2; i2++)
#pragma unroll
        for (int j = 0; j < 4; j++)
#pragma unroll
            for (int q = 0; q < 4; q++) acc[i2][j][q] = 0.0f;

    for (int c = 0; c < SG_CHUNKS; c++) {
        if (c + 1 < SG_CHUNKS) {
            uint32_t sb = smB + ((c + 1) & 1) * SG_BSTAGE;
            load_tile<128>(g_wcombh, CAT4, n0, NS, kseg + (c + 1) * BK, sb,             tid);
            load_tile<128>(g_wcombl, CAT4, n0, NS, kseg + (c + 1) * BK, sb + SG_TILE_B, tid);
            cp_commit();
            cp_wait1();
        } else {
            cp_wait0();
        }
        __syncthreads();

        const uint32_t sbA = smb + c * (2 * SG_TILE_A);
        const uint32_t sbB = smB + (c & 1) * SG_BSTAGE;
#pragma unroll
        for (int ks = 0; ks < 2; ks++) {
            const uint32_t kb = ks * 32 + (lane >> 4) * 16;
            uint32_t ah[2][4], al[2][4];
            const uint32_t arow = wm * 32 + (lane & 15);
#pragma unroll
            for (int ii = 0; ii < 2; ii++) {
                uint32_t ad = (arow + ii * 16) * SPADB + kb;
                ldmat4(ah[ii], sbA + ad);
                ldmat4(al[ii], sbA + SG_TILE_A + ad);
            }
            uint32_t bh[2][4], bl[2][4];
            const uint32_t brow = wn * 32 + (lane & 15);
#pragma unroll
            for (int p = 0; p < 2; p++) {
                uint32_t bd = (brow + p * 16) * SPADB + kb;
                ldmat4(bh[p], sbB + bd);
                ldmat4(bl[p], sbB + SG_TILE_B + bd);
            }
#pragma unroll
            for (int ii = 0; ii < 2; ii++)
#pragma unroll
                for (int j = 0; j < 4; j++) {
                    const int p = j >> 1, q = j & 1;
                    hmma(acc[ii][j], ah[ii], bh[p][q], bh[p][q + 2]);
                    hmma(acc[ii][j], ah[ii], bl[p][q], bl[p][q + 2]);
                    hmma(acc[ii][j], al[ii], bh[p][q], bh[p][q + 2]);
                }
        }
        __syncthreads();
    }

    // epilogue: direct store to partial S (bias folded into z==0 partial)
    float* C = g_Sp[z];
    const int rbase = wm * 32 + (lane >> 2);
    const int cbase = n0 + wn * 32 + (lane & 3) * 2;
#pragma unroll
    for (int ii = 0; ii < 2; ii++) {
#pragma unroll
        for (int j = 0; j < 4; j++) {
            int gc = cbase + j * 8;
#pragma unroll
            for (int half = 0; half < 2; half++) {
                int gr = rbase + ii * 16 + half * 8;
                float v0 = acc[ii][j][half * 2 + 0];
                float v1 = acc[ii][j][half * 2 + 1];
                if (z == 0) { v0 += g_bias_comb[gc]; v1 += g_bias_comb[gc + 1]; }
                float2 v = make_float2(v0, v1);
                *reinterpret_cast<float2*>(&C[gr * NS + gc]) = v;
            }
        }
    }
}

// ---------------- fused attention + cell (one block per batch, 512 threads) ----------------
__global__ void __launch_bounds__(512)
att_cell(const int* __restrict__ father_idx, const float* __restrict__ W_alpha,
         int i, int first, int use_f)
{
    const int b = blockIdx.x;
    const int tid = threadIdx.x;
    __shared__ float qs[Hh];
    __shared__ float wal[Hh];
    __shared__ float wsh[ATTN];
    __shared__ float red[512];

    float attc;
    if (!first) {
        // assemble query pre-activation from 4 partials
        {
            float q = 0.0f;
#pragma unroll
            for (int z = 0; z < 4; z++)
                q += g_Sp[z][b * NS + OFF_QA + tid] + g_Sp[z][b * NS + OFF_QF + tid];
            qs[tid] = q;
            wal[tid] = W_alpha[tid];
        }
        __syncthreads();

        // logits (b_alpha dropped: constant shift is softmax-invariant)
        const int wid = tid >> 5, lane = tid & 31;
        float4 q4[4], w4[4];
#pragma unroll
        for (int k = 0; k < 4; k++) {
            q4[k] = *(const float4*)&qs[4 * lane + 128 * k];
            w4[k] = *(const float4*)&wal[4 * lane + 128 * k];
        }
        for (int a = wid; a < ATTN; a += 16) {
            const float4* pa = (const float4*)(g_p_att + ((size_t)b * ATTN + a) * Hh);
            float sum = 0.0f;
#pragma unroll
            for (int k = 0; k < 4; k++) {
                float4 v = pa[lane + 32 * k];
                sum += w4[k].x * ftanh_fast(q4[k].x + v.x);
                sum += w4[k].y * ftanh_fast(q4[k].y + v.y);
                sum += w4[k].z * ftanh_fast(q4[k].z + v.z);
                sum += w4[k].w * ftanh_fast(q4[k].w + v.w);
            }
#pragma unroll
            for (int off = 16; off; off >>= 1)
                sum += __shfl_xor_sync(0xFFFFFFFFu, sum, off);
            if (lane == 0) wsh[a] = sum;
        }
        __syncthreads();

        // softmax over 196
        float lmx = (tid < ATTN) ? wsh[tid] : -3.4e38f;
        red[tid] = lmx; __syncthreads();
        for (int s = 256; s; s >>= 1) { if (tid < s) red[tid] = fmaxf(red[tid], red[tid + s]); __syncthreads(); }
        float mx = red[0]; __syncthreads();
        float e = (tid < ATTN) ? __expf(wsh[tid] - mx) : 0.0f;
        red[tid] = e; __syncthreads();
        for (int s = 256; s; s >>= 1) { if (tid < s) red[tid] += red[tid + s]; __syncthreads(); }
        float inv = 1.0f / red[0];
        __syncthreads();
        if (tid < ATTN) wsh[tid] = e * inv;
        __syncthreads();

        // weighted sum of projected attention features
        const float* pj = g_proj_att + ((size_t)b * ATTN) * Hh + tid;
        float acc = 0.0f;
#pragma unroll 4
        for (int a = 0; a < ATTN; a++)
            acc += wsh[a] * pj[(size_t)a * Hh];
        attc = acc;
    } else {
        attc = g_att_contrib0[b * Hh + tid];
    }

    // ---- cell pointwise (exact tanh/sigmoid) ----
    const int h = tid;
    float sIN = 0.f, sOUT = 0.f, sCG = 0.f, sF1 = 0.f, sF2 = 0.f;
#pragma unroll
    for (int z = 0; z < 4; z++) {
        const float* Sb = g_Sp[z] + b * NS;
        sIN  += Sb[OFF_IN  + h];
        sOUT += Sb[OFF_OUT + h];
        sCG  += Sb[OFF_CG  + h];
        sF1  += Sb[OFF_F1  + h];
        sF2  += Sb[OFF_F2  + h];
    }
    float ing  = fsigmoid(sIN);
    float outg = fsigmoid(sOUT);
    float cg   = ftanh(sCG + attc);

    float nc;
    if (first) {
        nc = ing * cg;
    } else {
        float f1 = fsigmoid(sF1);
        float f2 = fsigmoid(sF2);
        int father = father_idx[b * Tt + i];
        float c1 = g_c[((size_t)b * Tt + father) * Hh + h];
        float c2 = use_f ? g_c[((size_t)b * Tt + (i - 1)) * Hh + h] : 0.0f;
        nc = f1 * c1 + f2 * c2 + ing * cg;
    }
    float nh = outg * ftanh(nc);
    size_t o = ((size_t)b * Tt + i) * Hh + h;
    g_h[o] = nh;
    g_c[o] = nc;
    __nv_bfloat16 hb = __float2bfloat16(nh);
    g_hh[o] = hb;
    g_hl[o] = __float2bfloat16(nh - __bfloat162float(hb));
}

// ---------------- vectorized fp32 -> bf16 hi/lo split ----------------
__global__ void conv_hilo4(const float4* __restrict__ src,
                           uint2* __restrict__ hi, uint2* __restrict__ lo, int n4)
{
    int i = blockIdx.x * 256 + threadIdx.x;
    if (i < n4) {
        uint32_t h[2], l[2];
        pack_hilo4(src[i], h, l);
        hi[i] = make_uint2(h[0], h[1]);
        lo[i] = make_uint2(l[0], l[1]);
    }
}

// W_I attention columns [2048:4096), row stride 4096 (vectorized)
__global__ void conv_wproj4(const float* __restrict__ wI)
{
    int idx = blockIdx.x * 256 + threadIdx.x;   // Hh*AFd/4
    if (idx < Hh * AFd / 4) {
        int r = idx >> 9, k4 = (idx & 511) * 4;
        float4 v = *(const float4*)(wI + (size_t)r * 4096 + 2048 + k4);
        uint32_t h[2], l[2];
        pack_hilo4(v, h, l);
        ((uint2*)g_wprojh)[idx] = make_uint2(h[0], h[1]);
        ((uint2*)g_wprojl)[idx] = make_uint2(l[0], l[1]);
    }
}

// ---------------- combined weight build (vectorized, bf16 hi/lo) ----------------
__global__ void prep_wcomb4(const float* __restrict__ wH, const float* __restrict__ bH,
                            const float* __restrict__ wI, const float* __restrict__ bI,
                            const float* __restrict__ wf1, const float* __restrict__ bf1,
                            const float* __restrict__ wf2, const float* __restrict__ bf2,
                            const float* __restrict__ wha, const float* __restrict__ bha,
                            const float* __restrict__ whf, const float* __restrict__ bhf)
{
    int idx = blockIdx.x * 256 + threadIdx.x;
    if (idx < NS * CAT4 / 4) {
        int r = idx >> 9;
        int k = (idx & 511) * 4;
        float4 v = make_float4(0.f, 0.f, 0.f, 0.f);
        if (r < 1024) {
            v = *(const float4*)(wH + (size_t)r * 2048 + k);
        } else if (r < 1536) {
            v = *(const float4*)(wI + (size_t)(r - 1024) * 4096 + k);
        } else if (r < 2048) {
            int rr = r - 1536;
            if (k < 512)                    v = *(const float4*)(wf1 + rr * 1024 + k);
            else if (k >= 1024 && k < 1536) v = *(const float4*)(wf1 + rr * 1024 + 512 + (k - 1024));
        } else if (r < 2560) {
            int rr = r - 2048;
            if (k >= 512 && k < 1024)       v = *(const float4*)(wf2 + rr * 1024 + (k - 512));
            else if (k >= 1536)             v = *(const float4*)(wf2 + rr * 1024 + 512 + (k - 1536));
        } else if (r < 3072) {
            int rr = r - 2560;
            if (k >= 1024 && k < 1536)      v = *(const float4*)(wha + rr * 512 + (k - 1024));
        } else {
            int rr = r - 3072;
            if (k >= 1536)                  v = *(const float4*)(whf + rr * 512 + (k - 1536));
        }
        uint32_t h[2], l[2];
        pack_hilo4(v, h, l);
        ((uint2*)g_wcombh)[idx] = make_uint2(h[0], h[1]);
        ((uint2*)g_wcombl)[idx] = make_uint2(l[0], l[1]);
    }
    if (idx < NS) {
        int r = idx;
        float bv;
        if (r < 1024)      bv = bH[r];
        else if (r < 1536) bv = bI[r - 1024];
        else if (r < 2048) bv = bf1[r - 1536];
        else if (r < 2560) bv = bf2[r - 2048];
        else if (r < 3072) bv = bha[r - 2560];
        else               bv = bhf[r - 3072];
        g_bias_comb[r] = bv;
    }
}

__global__ void zero_hc4() {
    int idx = blockIdx.x * 256 + threadIdx.x;
    if (idx < Bb * Tt * Hh / 4) {
        ((float4*)g_h)[idx] = make_float4(0.f, 0.f, 0.f, 0.f);
        ((float4*)g_c)[idx] = make_float4(0.f, 0.f, 0.f, 0.f);
    }
}

__global__ void contrib0_kernel() {
    int b = blockIdx.x;
    int d = blockIdx.y * 256 + threadIdx.x;
    const float* pj = g_proj_att + ((size_t)b * ATTN) * Hh + d;
    float s = 0.0f;
#pragma unroll 4
    for (int a = 0; a < ATTN; a++) s += pj[(size_t)a * Hh];
    g_att_contrib0[b * Hh + d] = s * (1.0f / (float)ATTN);
}

__global__ void logsoftmax_kernel(float* __restrict__ out)
{
    int row = blockIdx.x;
    float* p = out + (size_t)row * Vv;
    int tx = threadIdx.x;
    __shared__ float red[256];

    float mx = -3.4e38f;
    for (int j = tx; j < Vv; j += 256) mx = fmaxf(mx, p[j]);
    red[tx] = mx; __syncthreads();
    for (int s = 128; s; s >>= 1) { if (tx < s) red[tx] = fmaxf(red[tx], red[tx + s]); __syncthreads(); }
    mx = red[0]; __syncthreads();

    float sum = 0.0f;
    for (int j = tx; j < Vv; j += 256) sum += __expf(p[j] - mx);
    red[tx] = sum; __syncthreads();
    for (int s = 128; s; s >>= 1) { if (tx < s) red[tx] += red[tx + s]; __syncthreads(); }
    float lse = mx + __logf(red[0]);
    __syncthreads();

    for (int j = tx; j < Vv; j += 256) p[j] -= lse;
}

// ---------------- host ----------------
extern "C" void kernel_launch(void* const* d_in, const int* in_sizes, int n_in,
                              void* d_out, int out_size)
{
    const int*   word_idx   = (const int*)  d_in[0];
    const int*   father_idx = (const int*)  d_in[1];
    const float* fc_feats   = (const float*)d_in[2];
    const float* att_feats  = (const float*)d_in[3];
    const float* W_fc       = (const float*)d_in[4];
    const float* b_fc       = (const float*)d_in[5];
    const float* W_att      = (const float*)d_in[6];
    const float* b_att      = (const float*)d_in[7];
    const float* embed_tab  = (const float*)d_in[8];
    const float* wf1        = (const float*)d_in[9];
    const float* bf1        = (const float*)d_in[10];
    const float* wf2        = (const float*)d_in[11];
    const float* bf2        = (const float*)d_in[12];
    const float* wH         = (const float*)d_in[13];
    const float* bH         = (const float*)d_in[14];
    const float* wI         = (const float*)d_in[15];
    const float* bI         = (const float*)d_in[16];
    const float* W_ha       = (const float*)d_in[17];
    const float* b_ha       = (const float*)d_in[18];
    const float* W_hf       = (const float*)d_in[19];
    const float* b_hf       = (const float*)d_in[20];
    const float* W_alpha    = (const float*)d_in[21];
    const float* b_alpha    = (const float*)d_in[22];
    const float* W_logit    = (const float*)d_in[23];
    const float* b_logit    = (const float*)d_in[24];
    float* out = (float*)d_out;
    (void)W_ha; (void)b_ha; (void)W_hf; (void)b_hf; (void)b_alpha;

    cudaFuncSetAttribute(tgemm<128>, cudaFuncAttributeMaxDynamicSharedMemorySize, TG<128>::SMEM);
    cudaFuncSetAttribute(tgemm<64>,  cudaFuncAttributeMaxDynamicSharedMemorySize, TG<64>::SMEM);
    cudaFuncSetAttribute(step_gemm,  cudaFuncAttributeMaxDynamicSharedMemorySize, SG_SMEM);

    void *p_fc, *p_patt, *p_proj;
    void *p_attfh, *p_attfl, *p_fcfh, *p_fcfl, *p_watth, *p_wattl, *p_wfch, *p_wfcl;
    void *p_wprojh, *p_wprojl, *p_wlgh, *p_wlgl, *p_hh, *p_hl;
    cudaGetSymbolAddress(&p_fc,     g_fc_emb);
    cudaGetSymbolAddress(&p_patt,   g_p_att);
    cudaGetSymbolAddress(&p_proj,   g_proj_att);
    cudaGetSymbolAddress(&p_attfh,  g_attfh);
    cudaGetSymbolAddress(&p_attfl,  g_attfl);
    cudaGetSymbolAddress(&p_fcfh,   g_fcfh);
    cudaGetSymbolAddress(&p_fcfl,   g_fcfl);
    cudaGetSymbolAddress(&p_watth,  g_watth);
    cudaGetSymbolAddress(&p_wattl,  g_wattl);
    cudaGetSymbolAddress(&p_wfch,   g_wfch);
    cudaGetSymbolAddress(&p_wfcl,   g_wfcl);
    cudaGetSymbolAddress(&p_wprojh, g_wprojh);
    cudaGetSymbolAddress(&p_wprojl, g_wprojl);
    cudaGetSymbolAddress(&p_wlgh,   g_wlgh);
    cudaGetSymbolAddress(&p_wlgl,   g_wlgl);
    cudaGetSymbolAddress(&p_hh,     g_hh);
    cudaGetSymbolAddress(&p_hl,     g_hl);

#define BF16P(x) ((__nv_bfloat16*)(x))

    // ---- prep: conversions + combined weight ----
    zero_hc4<<<(Bb * Tt * Hh / 4 + 255) / 256, 256>>>();
    conv_hilo4<<<(Bb * ATTN * AFd / 4 + 255) / 256, 256>>>((const float4*)att_feats, (uint2*)p_attfh, (uint2*)p_attfl, Bb * ATTN * AFd / 4);
    conv_hilo4<<<(Bb * FCd / 4 + 255) / 256, 256>>>((const float4*)fc_feats, (uint2*)p_fcfh, (uint2*)p_fcfl, Bb * FCd / 4);
    conv_hilo4<<<(Hh * AFd / 4 + 255) / 256, 256>>>((const float4*)W_att, (uint2*)p_watth, (uint2*)p_wattl, Hh * AFd / 4);
    conv_hilo4<<<(Ee * FCd / 4 + 255) / 256, 256>>>((const float4*)W_fc, (uint2*)p_wfch, (uint2*)p_wfcl, Ee * FCd / 4);
    conv_hilo4<<<(Vv * Hh / 4 + 255) / 256, 256>>>((const float4*)W_logit, (uint2*)p_wlgh, (uint2*)p_wlgl, Vv * Hh / 4);
    conv_wproj4<<<(Hh * AFd / 4 + 255) / 256, 256>>>(wI);
    prep_wcomb4<<<(NS * CAT4 / 4 + 255) / 256, 256>>>(wH, bH, wI, bI, wf1, bf1,
                                                      wf2, bf2, W_ha, b_ha, W_hf, b_hf);

    // fc_emb = fc_feats @ W_fc^T + b_fc     (64 x 512, K=2048)
    tgemm<64><<<dim3(1, 4, 1), 256, TG<64>::SMEM>>>(BF16P(p_fcfh), BF16P(p_fcfl), FCd,
                                                    BF16P(p_wfch), BF16P(p_wfcl), FCd,
                                                    b_fc, (float*)p_fc, Ee, Bb, Ee, FCd);
    // p_att = att_feats @ W_att^T + b_att   (12544 x 512, K=2048)
    tgemm<128><<<dim3(98, 4, 1), 256, TG<128>::SMEM>>>(BF16P(p_attfh), BF16P(p_attfl), AFd,
                                                       BF16P(p_watth), BF16P(p_wattl), AFd,
                                                       b_att, (float*)p_patt, Hh, Bb * ATTN, Hh, AFd);
    // proj_att = att_feats @ W_I_att^T      (12544 x 512, K=2048)
    tgemm<128><<<dim3(98, 4, 1), 256, TG<128>::SMEM>>>(BF16P(p_attfh), BF16P(p_attfl), AFd,
                                                       BF16P(p_wprojh), BF16P(p_wprojl), AFd,
                                                       nullptr, (float*)p_proj, Hh, Bb * ATTN, Hh, AFd);
    contrib0_kernel<<<dim3(Bb, 2), 256>>>();

    // ---- recurrent loop: 2 kernels per step ----
    for (int i = 0; i < Tt; ++i) {
        int first = (i == 0) ? 1 : 0;
        int use_f = (i > 0 && ((i - 1) % 3) != 0) ? 1 : 0;

        step_gemm<<<dim3(1, 28, 4), 256, SG_SMEM>>>(word_idx, father_idx, embed_tab, i, first, use_f);
        att_cell<<<Bb, 512>>>(father_idx, W_alpha, i, first, use_f);
    }

    // ---- logits + log_softmax ----
    tgemm<128><<<dim3(24, 79, 1), 256, TG<128>::SMEM>>>(BF16P(p_hh), BF16P(p_hl), Hh,
                                                        BF16P(p_wlgh), BF16P(p_wlgl), Hh,
                                                        b_logit, out, Vv, Bb * Tt, Vv, Hh);
    logsoftmax_kernel<<<Bb * Tt, 256>>>(out);
}

// round 17
// speedup vs baseline: 1.5861x; 1.0061x over previous
#include <cuda_runtime.h>
#include <cuda_bf16.h>
#include <math.h>
#include <stdint.h>

// ---------------- shapes ----------------
#define Bb   64
#define Tt   48
#define Hh   512
#define Ee   512
#define ATTN 196
#define AFd  2048
#define FCd  2048
#define Vv   10000
#define CAT4 2048
#define NS   3584

#define OFF_IN   0
#define OFF_OUT  512
#define OFF_CG   1024
#define OFF_F1   1536
#define OFF_F2   2048
#define OFF_QA   2560
#define OFF_QF   3072

// ---------------- tgemm tiling (mma.sync path, baseline PTX) ----------------
#define BN 128
#define BK 32                         // bf16 K per chunk
#define SPADB 80                      // padded smem row stride in BYTES (40 bf16)

template <int BMT>
struct TG {
    static constexpr int TILE_A  = BMT * SPADB;
    static constexpr int TILE_BB = 128 * SPADB;
    static constexpr int STAGE   = 2 * TILE_A + 2 * TILE_BB;
    static constexpr int SMEM    = 2 * STAGE;
};

// step_gemm smem layout
#define SG_TILE_A  (64 * SPADB)                   // 5120
#define SG_CHUNKS  16
#define SG_ABYTES  (SG_CHUNKS * 2 * SG_TILE_A)    // 163840
#define SG_TILE_B  (128 * SPADB)                  // 10240
#define SG_BSTAGE  (2 * SG_TILE_B)                // 20480
#define SG_SMEM    (SG_ABYTES + 2 * SG_BSTAGE)    // 204800

// ---------------- device scratch ----------------
__device__ float g_fc_emb[Bb * Ee];
__device__ float g_p_att[Bb * ATTN * Hh];
__device__ float g_proj_att[Bb * ATTN * Hh];
__device__ float g_bias_comb[NS];
__device__ float g_Sp[4][Bb * NS];
__device__ float g_att_contrib0[Bb * Hh];
__device__ float g_h[Bb * Tt * Hh];
__device__ float g_c[Bb * Tt * Hh];

__device__ __align__(128) __nv_bfloat16 g_attfh[Bb * ATTN * AFd];
__device__ __align__(128) __nv_bfloat16 g_attfl[Bb * ATTN * AFd];
__device__ __align__(128) __nv_bfloat16 g_fcfh[Bb * FCd];
__device__ __align__(128) __nv_bfloat16 g_fcfl[Bb * FCd];
__device__ __align__(128) __nv_bfloat16 g_watth[Hh * AFd];
__device__ __align__(128) __nv_bfloat16 g_wattl[Hh * AFd];
__device__ __align__(128) __nv_bfloat16 g_wfch[Ee * FCd];
__device__ __align__(128) __nv_bfloat16 g_wfcl[Ee * FCd];
__device__ __align__(128) __nv_bfloat16 g_wprojh[Hh * AFd];
__device__ __align__(128) __nv_bfloat16 g_wprojl[Hh * AFd];
__device__ __align__(128) __nv_bfloat16 g_wcombh[NS * CAT4];
__device__ __align__(128) __nv_bfloat16 g_wcombl[NS * CAT4];
__device__ __align__(128) __nv_bfloat16 g_wlgh[Vv * Hh];
__device__ __align__(128) __nv_bfloat16 g_wlgl[Vv * Hh];
__device__ __align__(128) __nv_bfloat16 g_hh[Bb * Tt * Hh];
__device__ __align__(128) __nv_bfloat16 g_hl[Bb * Tt * Hh];

// ---------------- math helpers ----------------
__device__ __forceinline__ float fsigmoid(float x) { return 1.0f / (1.0f + __expf(-x)); }
__device__ __forceinline__ float ftanh(float x) {
    float e = __expf(2.0f * x);
    return 1.0f - 2.0f / (e + 1.0f);
}
__device__ __forceinline__ float ftanh_fast(float x) {
    float y;
    asm("tanh.approx.f32 %0, %1;" : "=f"(y) : "f"(x));
    return y;
}

// ---------------- baseline-PTX tensor-core helpers ----------------
__device__ __forceinline__ uint32_t smem_u32(const void* p) {
    uint32_t a;
    asm("{ .reg .u64 t; cvta.to.shared.u64 t, %1; cvt.u32.u64 %0, t; }" : "=r"(a) : "l"(p));
    return a;
}
__device__ __forceinline__ void cp16(uint32_t dst, const void* src, int srcsize) {
    asm volatile("cp.async.cg.shared.global [%0], [%1], 16, %2;"
                 :: "r"(dst), "l"(src), "r"(srcsize));
}
__device__ __forceinline__ void cp_commit() { asm volatile("cp.async.commit_group;"); }
__device__ __forceinline__ void cp_wait1()  { asm volatile("cp.async.wait_group 1;"); }
__device__ __forceinline__ void cp_wait0()  { asm volatile("cp.async.wait_group 0;"); }

__device__ __forceinline__ void ldmat4(uint32_t r[4], uint32_t addr) {
    asm volatile("ldmatrix.sync.aligned.m8n8.x4.shared.b16 {%0,%1,%2,%3}, [%4];"
                 : "=r"(r[0]), "=r"(r[1]), "=r"(r[2]), "=r"(r[3]) : "r"(addr));
}
__device__ __forceinline__ void hmma(float c[4], const uint32_t a[4], uint32_t b0, uint32_t b1) {
    asm volatile(
        "mma.sync.aligned.m16n8k16.row.col.f32.bf16.bf16.f32 "
        "{%0,%1,%2,%3}, {%4,%5,%6,%7}, {%8,%9}, {%0,%1,%2,%3};"
        : "+f"(c[0]), "+f"(c[1]), "+f"(c[2]), "+f"(c[3])
        : "r"(a[0]), "r"(a[1]), "r"(a[2]), "r"(a[3]), "r"(b0), "r"(b1));
}

// pack 4 floats -> two bf16x2 words (hi) + two bf16x2 words (lo residual)
__device__ __forceinline__ void pack_hilo4(float4 v, uint32_t h[2], uint32_t l[2]) {
    __nv_bfloat162 h0 = __floats2bfloat162_rn(v.x, v.y);
    __nv_bfloat162 h1 = __floats2bfloat162_rn(v.z, v.w);
    __nv_bfloat162 l0 = __floats2bfloat162_rn(v.x - __low2float(h0), v.y - __high2float(h0));
    __nv_bfloat162 l1 = __floats2bfloat162_rn(v.z - __low2float(h1), v.w - __high2float(h1));
    h[0] = *(uint32_t*)&h0; h[1] = *(uint32_t*)&h1;
    l[0] = *(uint32_t*)&l0; l[1] = *(uint32_t*)&l1;
}

// ---------------- tile loader: ROWS x 32 bf16 (64B/row), cp.async ----------------
template <int ROWS>
__device__ __forceinline__ void load_tile(const __nv_bfloat16* __restrict__ G, int ld,
                                          int row0, int rowmax, int kt,
                                          uint32_t sm, int tid)
{
#pragma unroll
    for (int t = 0; t < ROWS / 64; t++) {
        int idx = tid + t * 256;
        int r = idx >> 2, c = idx & 3;
        int gr = row0 + r;
        int ok = (gr < rowmax);
        const void* src = G + (size_t)(ok ? gr : 0) * ld + kt + c * 8;
        cp16(sm + r * SPADB + c * 16, src, ok ? 16 : 0);
    }
}

// ---------------- generic bf16x3 tensor-core GEMM (prep + logits) ----------------
template <int BMT>
__global__ void __launch_bounds__(256)
tgemm(const __nv_bfloat16* __restrict__ Ah, const __nv_bfloat16* __restrict__ Al, int lda,
      const __nv_bfloat16* __restrict__ Bh, const __nv_bfloat16* __restrict__ Bl, int ldb,
      const float* __restrict__ bias, float* __restrict__ C, int ldc,
      int M, int N, int K)
{
    constexpr int IFR     = BMT / 32;
    constexpr int TILE_A  = TG<BMT>::TILE_A;
    constexpr int TILE_BB = TG<BMT>::TILE_BB;
    constexpr int STAGE   = TG<BMT>::STAGE;

    extern __shared__ char dsm[];
    const uint32_t smb = smem_u32(dsm);

    const int tid  = threadIdx.x;
    const int wid  = tid >> 5, lane = tid & 31;
    const int wm   = wid & 1;
    const int wn   = wid >> 1;
    const int m0   = blockIdx.x * BMT;
    const int n0   = blockIdx.y * BN;
    const int nchunks = K / BK;

    float acc[IFR][4][4];
#pragma unroll
    for (int i = 0; i < IFR; i++)
#pragma unroll
        for (int j = 0; j < 4; j++)
#pragma unroll
            for (int q = 0; q < 4; q++) acc[i][j][q] = 0.0f;

    {
        uint32_t sb = smb;
        load_tile<BMT>(Ah, lda, m0, M, 0, sb,                        tid);
        load_tile<BMT>(Al, lda, m0, M, 0, sb + TILE_A,               tid);
        load_tile<128>(Bh, ldb, n0, N, 0, sb + 2 * TILE_A,           tid);
        load_tile<128>(Bl, ldb, n0, N, 0, sb + 2 * TILE_A + TILE_BB, tid);
        cp_commit();
    }

    for (int c = 0; c < nchunks; c++) {
        if (c + 1 < nchunks) {
            uint32_t sb = smb + ((c + 1) & 1) * STAGE;
            int kt = (c + 1) * BK;
            load_tile<BMT>(Ah, lda, m0, M, kt, sb,                        tid);
            load_tile<BMT>(Al, lda, m0, M, kt, sb + TILE_A,               tid);
            load_tile<128>(Bh, ldb, n0, N, kt, sb + 2 * TILE_A,           tid);
            load_tile<128>(Bl, ldb, n0, N, kt, sb + 2 * TILE_A + TILE_BB, tid);
            cp_commit();
            cp_wait1();
        } else {
            cp_wait0();
        }
        __syncthreads();

        const uint32_t sb = smb + (c & 1) * STAGE;
#pragma unroll
        for (int ks = 0; ks < 2; ks++) {
            const uint32_t kb = ks * 32 + (lane >> 4) * 16;
            uint32_t ah[IFR][4], al[IFR][4];
            const uint32_t arow = wm * (BMT / 2) + (lane & 15);
#pragma unroll
            for (int i = 0; i < IFR; i++) {
                uint32_t ad = (arow + i * 16) * SPADB + kb;
                ldmat4(ah[i], sb + ad);
                ldmat4(al[i], sb + TILE_A + ad);
            }
            uint32_t bh[2][4], bl[2][4];
            const uint32_t brow = wn * 32 + (lane & 15);
#pragma unroll
            for (int p = 0; p < 2; p++) {
                uint32_t bd = (brow + p * 16) * SPADB + kb;
                ldmat4(bh[p], sb + 2 * TILE_A + bd);
                ldmat4(bl[p], sb + 2 * TILE_A + TILE_BB + bd);
            }
#pragma unroll
            for (int i = 0; i < IFR; i++)
#pragma unroll
                for (int j = 0; j < 4; j++) {
                    const int p = j >> 1, q = j & 1;
                    hmma(acc[i][j], ah[i], bh[p][q], bh[p][q + 2]);
                    hmma(acc[i][j], ah[i], bl[p][q], bl[p][q + 2]);
                    hmma(acc[i][j], al[i], bh[p][q], bh[p][q + 2]);
                }
        }
        __syncthreads();
    }

    const int rbase = m0 + wm * (BMT / 2) + (lane >> 2);
    const int cbase = n0 + wn * 32 + (lane & 3) * 2;
#pragma unroll
    for (int i = 0; i < IFR; i++) {
#pragma unroll
        for (int j = 0; j < 4; j++) {
            int gc = cbase + j * 8;
#pragma unroll
            for (int half = 0; half < 2; half++) {
                int gr = rbase + i * 16 + half * 8;
                if (gr >= M || gc >= N) continue;
                float v0 = acc[i][j][half * 2 + 0];
                float v1 = acc[i][j][half * 2 + 1];
                if (bias) { v0 += bias[gc]; if (gc + 1 < N) v1 += bias[gc + 1]; }
                float* dst = C + (size_t)gr * ldc + gc;
                if (gc + 1 < N) { float2 v = make_float2(v0, v1); *reinterpret_cast<float2*>(dst) = v; }
                else dst[0] = v0;
            }
        }
    }
}

// ---------------- fused per-step GEMM: gather + bf16x3 MMA -> partial S ----------------
// grid (1, 28, 4): y = 128-col tile of NS, z = cat4 segment {x1, x2, h1, h2}
__global__ void __launch_bounds__(256)
step_gemm(const int* __restrict__ word_idx, const int* __restrict__ father_idx,
          const float* __restrict__ embed_tab, int i, int first, int use_f)
{
    extern __shared__ char dsm[];
    __shared__ const float* srcrow[64];

    const int tid = threadIdx.x;
    const int wid = tid >> 5, lane = tid & 31;
    const int wm  = wid & 1;
    const int wn  = wid >> 1;
    const int z   = blockIdx.z;
    const int n0  = blockIdx.y * 128;
    const int kseg = z * 512;

    const uint32_t smb = smem_u32(dsm);
    const uint32_t smB = smb + SG_ABYTES;

    // per-row source pointers for this segment
    if (tid < 64) {
        int b = tid;
        const float* p = nullptr;
        if (z == 0) {
            if (first) p = g_fc_emb + b * Ee;
            else {
                int father = father_idx[b * Tt + i];
                int w = word_idx[b * Tt + father];
                p = embed_tab + (size_t)w * Ee;
            }
        } else if (z == 1) {
            if (use_f) {
                int w = word_idx[b * Tt + (i - 1)];
                p = embed_tab + (size_t)w * Ee;
            }
        } else if (z == 2) {
            if (!first) {
                int father = father_idx[b * Tt + i];
                p = g_h + ((size_t)b * Tt + father) * Hh;
            }
        } else {
            if (use_f) p = g_h + ((size_t)b * Tt + (i - 1)) * Hh;
        }
        srcrow[b] = p;
    }

    // kick off B chunk 0 while we gather A
    load_tile<128>(g_wcombh, CAT4, n0, NS, kseg, smB,              tid);
    load_tile<128>(g_wcombl, CAT4, n0, NS, kseg, smB + SG_TILE_B,  tid);
    cp_commit();
    __syncthreads();   // srcrow visible

    // gather A segment: 64 x 512 fp32 -> hi/lo bf16, chunk-tiled smem
#pragma unroll 4
    for (int t = 0; t < 32; t++) {
        int idx = t * 256 + tid;            // 8192 float4 slots
        int r = idx >> 7;                    // 128 float4 per row
        int c4 = (idx & 127) * 4;
        const float* p = srcrow[r];
        float4 v = p ? *(const float4*)(p + c4) : make_float4(0.f, 0.f, 0.f, 0.f);
        uint32_t h[2], l[2];
        pack_hilo4(v, h, l);
        int ch = c4 >> 5, cc = c4 & 31;
        char* base = dsm + ch * (2 * SG_TILE_A) + r * SPADB + cc * 2;
        *(uint32_t*)(base)                  = h[0];
        *(uint32_t*)(base + 4)              = h[1];
        *(uint32_t*)(base + SG_TILE_A)      = l[0];
        *(uint32_t*)(base + SG_TILE_A + 4)  = l[1];
    }

    float acc[2][4][4];
#pragma unroll
    for (int i2 = 0; i2 < 2; i2++)
#pragma unroll
        for (int j = 0; j < 4; j++)
#pragma unroll
            for (int q = 0; q < 4; q++) acc[i2][j][q] = 0.0f;

    for (int c = 0; c < SG_CHUNKS; c++) {
        if (c + 1 < SG_CHUNKS) {
            uint32_t sb = smB + ((c + 1) & 1) * SG_BSTAGE;
            load_tile<128>(g_wcombh, CAT4, n0, NS, kseg + (c + 1) * BK, sb,             tid);
            load_tile<128>(g_wcombl, CAT4, n0, NS, kseg + (c + 1) * BK, sb + SG_TILE_B, tid);
            cp_commit();
            cp_wait1();
        } else {
            cp_wait0();
        }
        __syncthreads();

        const uint32_t sbA = smb + c * (2 * SG_TILE_A);
        const uint32_t sbB = smB + (c & 1) * SG_BSTAGE;
#pragma unroll
        for (int ks = 0; ks < 2; ks++) {
            const uint32_t kb = ks * 32 + (lane >> 4) * 16;
            uint32_t ah[2][4], al[2][4];
            const uint32_t arow = wm * 32 + (lane & 15);
#pragma unroll
            for (int ii = 0; ii < 2; ii++) {
                uint32_t ad = (arow + ii * 16) * SPADB + kb;
                ldmat4(ah[ii], sbA + ad);
                ldmat4(al[ii], sbA + SG_TILE_A + ad);
            }
            uint32_t bh[2][4], bl[2][4];
            const uint32_t brow = wn * 32 + (lane & 15);
#pragma unroll
            for (int p = 0; p < 2; p++) {
                uint32_t bd = (brow + p * 16) * SPADB + kb;
                ldmat4(bh[p], sbB + bd);
                ldmat4(bl[p], sbB + SG_TILE_B + bd);
            }
#pragma unroll
            for (int ii = 0; ii < 2; ii++)
#pragma unroll
                for (int j = 0; j < 4; j++) {
                    const int p = j >> 1, q = j & 1;
                    hmma(acc[ii][j], ah[ii], bh[p][q], bh[p][q + 2]);
                    hmma(acc[ii][j], ah[ii], bl[p][q], bl[p][q + 2]);
                    hmma(acc[ii][j], al[ii], bh[p][q], bh[p][q + 2]);
                }
        }
        __syncthreads();
    }

    // epilogue: direct store to partial S (bias folded into z==0 partial)
    float* C = g_Sp[z];
    const int rbase = wm * 32 + (lane >> 2);
    const int cbase = n0 + wn * 32 + (lane & 3) * 2;
#pragma unroll
    for (int ii = 0; ii < 2; ii++) {
#pragma unroll
        for (int j = 0; j < 4; j++) {
            int gc = cbase + j * 8;
#pragma unroll
            for (int half = 0; half < 2; half++) {
                int gr = rbase + ii * 16 + half * 8;
                float v0 = acc[ii][j][half * 2 + 0];
                float v1 = acc[ii][j][half * 2 + 1];
                if (z == 0) { v0 += g_bias_comb[gc]; v1 += g_bias_comb[gc + 1]; }
                float2 v = make_float2(v0, v1);
                *reinterpret_cast<float2*>(&C[gr * NS + gc]) = v;
            }
        }
    }
}

// ---------------- fused attention + cell (one block per batch, 512 threads) ----------------
__global__ void __launch_bounds__(512)
att_cell(const int* __restrict__ father_idx, const float* __restrict__ W_alpha,
         int i, int first, int use_f)
{
    const int b = blockIdx.x;
    const int tid = threadIdx.x;
    __shared__ float qs[Hh];
    __shared__ float wal[Hh];
    __shared__ float wsh[ATTN];
    __shared__ float red[512];

    float attc;
    if (!first) {
        // assemble query pre-activation from 4 partials
        {
            float q = 0.0f;
#pragma unroll
            for (int z = 0; z < 4; z++)
                q += g_Sp[z][b * NS + OFF_QA + tid] + g_Sp[z][b * NS + OFF_QF + tid];
            qs[tid] = q;
            wal[tid] = W_alpha[tid];
        }
        __syncthreads();

        // logits (b_alpha dropped: constant shift is softmax-invariant)
        const int wid = tid >> 5, lane = tid & 31;
        float4 q4[4], w4[4];
#pragma unroll
        for (int k = 0; k < 4; k++) {
            q4[k] = *(const float4*)&qs[4 * lane + 128 * k];
            w4[k] = *(const float4*)&wal[4 * lane + 128 * k];
        }
        for (int a = wid; a < ATTN; a += 16) {
            const float4* pa = (const float4*)(g_p_att + ((size_t)b * ATTN + a) * Hh);
            float sum = 0.0f;
#pragma unroll
            for (int k = 0; k < 4; k++) {
                float4 v = pa[lane + 32 * k];
                sum += w4[k].x * ftanh_fast(q4[k].x + v.x);
                sum += w4[k].y * ftanh_fast(q4[k].y + v.y);
                sum += w4[k].z * ftanh_fast(q4[k].z + v.z);
                sum += w4[k].w * ftanh_fast(q4[k].w + v.w);
            }
#pragma unroll
            for (int off = 16; off; off >>= 1)
                sum += __shfl_xor_sync(0xFFFFFFFFu, sum, off);
            if (lane == 0) wsh[a] = sum;
        }
        __syncthreads();

        // softmax over 196
        float lmx = (tid < ATTN) ? wsh[tid] : -3.4e38f;
        red[tid] = lmx; __syncthreads();
        for (int s = 256; s; s >>= 1) { if (tid < s) red[tid] = fmaxf(red[tid], red[tid + s]); __syncthreads(); }
        float mx = red[0]; __syncthreads();
        float e = (tid < ATTN) ? __expf(wsh[tid] - mx) : 0.0f;
        red[tid] = e; __syncthreads();
        for (int s = 256; s; s >>= 1) { if (tid < s) red[tid] += red[tid + s]; __syncthreads(); }
        float inv = 1.0f / red[0];
        __syncthreads();
        if (tid < ATTN) wsh[tid] = e * inv;
        __syncthreads();

        // weighted sum of projected attention features
        const float* pj = g_proj_att + ((size_t)b * ATTN) * Hh + tid;
        float acc = 0.0f;
#pragma unroll 4
        for (int a = 0; a < ATTN; a++)
            acc += wsh[a] * pj[(size_t)a * Hh];
        attc = acc;
    } else {
        attc = g_att_contrib0[b * Hh + tid];
    }

    // ---- cell pointwise (exact tanh/sigmoid) ----
    const int h = tid;
    float sIN = 0.f, sOUT = 0.f, sCG = 0.f, sF1 = 0.f, sF2 = 0.f;
#pragma unroll
    for (int z = 0; z < 4; z++) {
        const float* Sb = g_Sp[z] + b * NS;
        sIN  += Sb[OFF_IN  + h];
        sOUT += Sb[OFF_OUT + h];
        sCG  += Sb[OFF_CG  + h];
        sF1  += Sb[OFF_F1  + h];
        sF2  += Sb[OFF_F2  + h];
    }
    float ing  = fsigmoid(sIN);
    float outg = fsigmoid(sOUT);
    float cg   = ftanh(sCG + attc);

    float nc;
    if (first) {
        nc = ing * cg;
    } else {
        float f1 = fsigmoid(sF1);
        float f2 = fsigmoid(sF2);
        int father = father_idx[b * Tt + i];
        float c1 = g_c[((size_t)b * Tt + father) * Hh + h];
        float c2 = use_f ? g_c[((size_t)b * Tt + (i - 1)) * Hh + h] : 0.0f;
        nc = f1 * c1 + f2 * c2 + ing * cg;
    }
    float nh = outg * ftanh(nc);
    size_t o = ((size_t)b * Tt + i) * Hh + h;
    g_h[o] = nh;
    g_c[o] = nc;
    __nv_bfloat16 hb = __float2bfloat16(nh);
    g_hh[o] = hb;
    g_hl[o] = __float2bfloat16(nh - __bfloat162float(hb));
}

// ---------------- vectorized fp32 -> bf16 hi/lo split ----------------
__global__ void conv_hilo4(const float4* __restrict__ src,
                           uint2* __restrict__ hi, uint2* __restrict__ lo, int n4)
{
    int i = blockIdx.x * 256 + threadIdx.x;
    if (i < n4) {
        uint32_t h[2], l[2];
        pack_hilo4(src[i], h, l);
        hi[i] = make_uint2(h[0], h[1]);
        lo[i] = make_uint2(l[0], l[1]);
    }
}

// W_I attention columns [2048:4096), row stride 4096 (vectorized)
__global__ void conv_wproj4(const float* __restrict__ wI)
{
    int idx = blockIdx.x * 256 + threadIdx.x;   // Hh*AFd/4
    if (idx < Hh * AFd / 4) {
        int r = idx >> 9, k4 = (idx & 511) * 4;
        float4 v = *(const float4*)(wI + (size_t)r * 4096 + 2048 + k4);
        uint32_t h[2], l[2];
        pack_hilo4(v, h, l);
        ((uint2*)g_wprojh)[idx] = make_uint2(h[0], h[1]);
        ((uint2*)g_wprojl)[idx] = make_uint2(l[0], l[1]);
    }
}

// ---------------- combined weight build (vectorized, bf16 hi/lo) ----------------
__global__ void prep_wcomb4(const float* __restrict__ wH, const float* __restrict__ bH,
                            const float* __restrict__ wI, const float* __restrict__ bI,
                            const float* __restrict__ wf1, const float* __restrict__ bf1,
                            const float* __restrict__ wf2, const float* __restrict__ bf2,
                            const float* __restrict__ wha, const float* __restrict__ bha,
                            const float* __restrict__ whf, const float* __restrict__ bhf)
{
    int idx = blockIdx.x * 256 + threadIdx.x;
    if (idx < NS * CAT4 / 4) {
        int r = idx >> 9;
        int k = (idx & 511) * 4;
        float4 v = make_float4(0.f, 0.f, 0.f, 0.f);
        if (r < 1024) {
            v = *(const float4*)(wH + (size_t)r * 2048 + k);
        } else if (r < 1536) {
            v = *(const float4*)(wI + (size_t)(r - 1024) * 4096 + k);
        } else if (r < 2048) {
            int rr = r - 1536;
            if (k < 512)                    v = *(const float4*)(wf1 + rr * 1024 + k);
            else if (k >= 1024 && k < 1536) v = *(const float4*)(wf1 + rr * 1024 + 512 + (k - 1024));
        } else if (r < 2560) {
            int rr = r - 2048;
            if (k >= 512 && k < 1024)       v = *(const float4*)(wf2 + rr * 1024 + (k - 512));
            else if (k >= 1536)             v = *(const float4*)(wf2 + rr * 1024 + 512 + (k - 1536));
        } else if (r < 3072) {
            int rr = r - 2560;
            if (k >= 1024 && k < 1536)      v = *(const float4*)(wha + rr * 512 + (k - 1024));
        } else {
            int rr = r - 3072;
            if (k >= 1536)                  v = *(const float4*)(whf + rr * 512 + (k - 1536));
        }
        uint32_t h[2], l[2];
        pack_hilo4(v, h, l);
        ((uint2*)g_wcombh)[idx] = make_uint2(h[0], h[1]);
        ((uint2*)g_wcombl)[idx] = make_uint2(l[0], l[1]);
    }
    if (idx < NS) {
        int r = idx;
        float bv;
        if (r < 1024)      bv = bH[r];
        else if (r < 1536) bv = bI[r - 1024];
        else if (r < 2048) bv = bf1[r - 1536];
        else if (r < 2560) bv = bf2[r - 2048];
        else if (r < 3072) bv = bha[r - 2560];
        else               bv = bhf[r - 3072];
        g_bias_comb[r] = bv;
    }
}

__global__ void zero_hc4() {
    int idx = blockIdx.x * 256 + threadIdx.x;
    if (idx < Bb * Tt * Hh / 4) {
        ((float4*)g_h)[idx] = make_float4(0.f, 0.f, 0.f, 0.f);
        ((float4*)g_c)[idx] = make_float4(0.f, 0.f, 0.f, 0.f);
    }
}

__global__ void contrib0_kernel() {
    int b = blockIdx.x;
    int d = blockIdx.y * 256 + threadIdx.x;
    const float* pj = g_proj_att + ((size_t)b * ATTN) * Hh + d;
    float s = 0.0f;
#pragma unroll 4
    for (int a = 0; a < ATTN; a++) s += pj[(size_t)a * Hh];
    g_att_contrib0[b * Hh + d] = s * (1.0f / (float)ATTN);
}

__global__ void logsoftmax_kernel(float* __restrict__ out)
{
    int row = blockIdx.x;
    float* p = out + (size_t)row * Vv;
    int tx = threadIdx.x;
    __shared__ float red[256];

    float mx = -3.4e38f;
    for (int j = tx; j < Vv; j += 256) mx = fmaxf(mx, p[j]);
    red[tx] = mx; __syncthreads();
    for (int s = 128; s; s >>= 1) { if (tx < s) red[tx] = fmaxf(red[tx], red[tx + s]); __syncthreads(); }
    mx = red[0]; __syncthreads();

    float sum = 0.0f;
    for (int j = tx; j < Vv; j += 256) sum += __expf(p[j] - mx);
    red[tx] = sum; __syncthreads();
    for (int s = 128; s; s >>= 1) { if (tx < s) red[tx] += red[tx + s]; __syncthreads(); }
    float lse = mx + __logf(red[0]);
    __syncthreads();

    for (int j = tx; j < Vv; j += 256) p[j] -= lse;
}

// ---------------- host ----------------
extern "C" void kernel_launch(void* const* d_in, const int* in_sizes, int n_in,
                              void* d_out, int out_size)
{
    const int*   word_idx   = (const int*)  d_in[0];
    const int*   father_idx = (const int*)  d_in[1];
    const float* fc_feats   = (const float*)d_in[2];
    const float* att_feats  = (const float*)d_in[3];
    const float* W_fc       = (const float*)d_in[4];
    const float* b_fc       = (const float*)d_in[5];
    const float* W_att      = (const float*)d_in[6];
    const float* b_att      = (const float*)d_in[7];
    const float* embed_tab  = (const float*)d_in[8];
    const float* wf1        = (const float*)d_in[9];
    const float* bf1        = (const float*)d_in[10];
    const float* wf2        = (const float*)d_in[11];
    const float* bf2        = (const float*)d_in[12];
    const float* wH         = (const float*)d_in[13];
    const float* bH         = (const float*)d_in[14];
    const float* wI         = (const float*)d_in[15];
    const float* bI         = (const float*)d_in[16];
    const float* W_ha       = (const float*)d_in[17];
    const float* b_ha       = (const float*)d_in[18];
    const float* W_hf       = (const float*)d_in[19];
    const float* b_hf       = (const float*)d_in[20];
    const float* W_alpha    = (const float*)d_in[21];
    const float* b_alpha    = (const float*)d_in[22];
    const float* W_logit    = (const float*)d_in[23];
    const float* b_logit    = (const float*)d_in[24];
    float* out = (float*)d_out;
    (void)W_ha; (void)b_ha; (void)W_hf; (void)b_hf; (void)b_alpha;

    cudaFuncSetAttribute(tgemm<128>, cudaFuncAttributeMaxDynamicSharedMemorySize, TG<128>::SMEM);
    cudaFuncSetAttribute(tgemm<64>,  cudaFuncAttributeMaxDynamicSharedMemorySize, TG<64>::SMEM);
    cudaFuncSetAttribute(step_gemm,  cudaFuncAttributeMaxDynamicSharedMemorySize, SG_SMEM);

    void *p_fc, *p_patt, *p_proj;
    void *p_attfh, *p_attfl, *p_fcfh, *p_fcfl, *p_watth, *p_wattl, *p_wfch, *p_wfcl;
    void *p_wprojh, *p_wprojl, *p_wlgh, *p_wlgl, *p_hh, *p_hl;
    cudaGetSymbolAddress(&p_fc,     g_fc_emb);
    cudaGetSymbolAddress(&p_patt,   g_p_att);
    cudaGetSymbolAddress(&p_proj,   g_proj_att);
    cudaGetSymbolAddress(&p_attfh,  g_attfh);
    cudaGetSymbolAddress(&p_attfl,  g_attfl);
    cudaGetSymbolAddress(&p_fcfh,   g_fcfh);
    cudaGetSymbolAddress(&p_fcfl,   g_fcfl);
    cudaGetSymbolAddress(&p_watth,  g_watth);
    cudaGetSymbolAddress(&p_wattl,  g_wattl);
    cudaGetSymbolAddress(&p_wfch,   g_wfch);
    cudaGetSymbolAddress(&p_wfcl,   g_wfcl);
    cudaGetSymbolAddress(&p_wprojh, g_wprojh);
    cudaGetSymbolAddress(&p_wprojl, g_wprojl);
    cudaGetSymbolAddress(&p_wlgh,   g_wlgh);
    cudaGetSymbolAddress(&p_wlgl,   g_wlgl);
    cudaGetSymbolAddress(&p_hh,     g_hh);
    cudaGetSymbolAddress(&p_hl,     g_hl);

#define BF16P(x) ((__nv_bfloat16*)(x))

    // ---- prep: conversions + combined weight ----
    zero_hc4<<<(Bb * Tt * Hh / 4 + 255) / 256, 256>>>();
    conv_hilo4<<<(Bb * ATTN * AFd / 4 + 255) / 256, 256>>>((const float4*)att_feats, (uint2*)p_attfh, (uint2*)p_attfl, Bb * ATTN * AFd / 4);
    conv_hilo4<<<(Bb * FCd / 4 + 255) / 256, 256>>>((const float4*)fc_feats, (uint2*)p_fcfh, (uint2*)p_fcfl, Bb * FCd / 4);
    conv_hilo4<<<(Hh * AFd / 4 + 255) / 256, 256>>>((const float4*)W_att, (uint2*)p_watth, (uint2*)p_wattl, Hh * AFd / 4);
    conv_hilo4<<<(Ee * FCd / 4 + 255) / 256, 256>>>((const float4*)W_fc, (uint2*)p_wfch, (uint2*)p_wfcl, Ee * FCd / 4);
    conv_hilo4<<<(Vv * Hh / 4 + 255) / 256, 256>>>((const float4*)W_logit, (uint2*)p_wlgh, (uint2*)p_wlgl, Vv * Hh / 4);
    conv_wproj4<<<(Hh * AFd / 4 + 255) / 256, 256>>>(wI);
    prep_wcomb4<<<(NS * CAT4 / 4 + 255) / 256, 256>>>(wH, bH, wI, bI, wf1, bf1,
                                                      wf2, bf2, W_ha, b_ha, W_hf, b_hf);

    // fc_emb = fc_feats @ W_fc^T + b_fc     (64 x 512, K=2048)
    tgemm<64><<<dim3(1, 4, 1), 256, TG<64>::SMEM>>>(BF16P(p_fcfh), BF16P(p_fcfl), FCd,
                                                    BF16P(p_wfch), BF16P(p_wfcl), FCd,
                                                    b_fc, (float*)p_fc, Ee, Bb, Ee, FCd);
    // p_att = att_feats @ W_att^T + b_att   (12544 x 512, K=2048)
    tgemm<128><<<dim3(98, 4, 1), 256, TG<128>::SMEM>>>(BF16P(p_attfh), BF16P(p_attfl), AFd,
                                                       BF16P(p_watth), BF16P(p_wattl), AFd,
                                                       b_att, (float*)p_patt, Hh, Bb * ATTN, Hh, AFd);
    // proj_att = att_feats @ W_I_att^T      (12544 x 512, K=2048)
    tgemm<128><<<dim3(98, 4, 1), 256, TG<128>::SMEM>>>(BF16P(p_attfh), BF16P(p_attfl), AFd,
                                                       BF16P(p_wprojh), BF16P(p_wprojl), AFd,
                                                       nullptr, (float*)p_proj, Hh, Bb * ATTN, Hh, AFd);
    contrib0_kernel<<<dim3(Bb, 2), 256>>>();

    // ---- recurrent loop: 2 kernels per step ----
    for (int i = 0; i < Tt; ++i) {
        int first = (i == 0) ? 1 : 0;
        int use_f = (i > 0 && ((i - 1) % 3) != 0) ? 1 : 0;

        step_gemm<<<dim3(1, 28, 4), 256, SG_SMEM>>>(word_idx, father_idx, embed_tab, i, first, use_f);
        att_cell<<<Bb, 512>>>(father_idx, W_alpha, i, first, use_f);
    }

    // ---- logits + log_softmax ----
    tgemm<128><<<dim3(24, 79, 1), 256, TG<128>::SMEM>>>(BF16P(p_hh), BF16P(p_hl), Hh,
                                                        BF16P(p_wlgh), BF16P(p_wlgl), Hh,
                                                        b_logit, out, Vv, Bb * Tt, Vv, Hh);
    logsoftmax_kernel<<<Bb * Tt, 256>>>(out);
}